// round 1
// baseline (speedup 1.0000x reference)
#include <cuda_runtime.h>
#include <cuda_bf16.h>
#include <cstdint>

#define NAc 131072
#define NWc 131072
#define Nc  262144
#define Ec  1048576
#define Hc  128
#define Rc  4

// ---------------- scratch (static __device__, no runtime alloc) ----------------
__device__ float g_hA[(size_t)Nc * Hc];           // 128 MB
__device__ float g_hB[(size_t)Nc * Hc];           // 128 MB
__device__ float g_agg[(size_t)Nc * Rc * Hc];     // 512 MB
__device__ float g_inv[(size_t)Nc * Rc];          // 4 MB
__device__ int   g_cnt[(size_t)Nc * Rc];          // 4 MB

// ---------------- edge-type counting ----------------
__global__ void count_kernel(const int* __restrict__ ei, const int* __restrict__ et,
                             int* __restrict__ cnt) {
    int e = blockIdx.x * blockDim.x + threadIdx.x;
    if (e < Ec) {
        int dst = ei[Ec + e];
        int r = et[e];
        atomicAdd(&cnt[dst * Rc + r], 1);
    }
}

__global__ void inv_kernel(const int* __restrict__ cnt, float* __restrict__ inv) {
    int i = blockIdx.x * blockDim.x + threadIdx.x;
    if (i < Nc * Rc) {
        int c = cnt[i];
        inv[i] = 1.0f / (float)(c > 0 ? c : 1);
    }
}

// ---------------- scatter: agg[dst][r] += h[src] * inv[dst][r] ----------------
// one warp per edge; 32 lanes x float4 = 128 floats
__global__ void __launch_bounds__(256) scatter_kernel(
    const float* __restrict__ h, const int* __restrict__ ei,
    const int* __restrict__ et, const float* __restrict__ inv,
    float* __restrict__ agg)
{
    int e = blockIdx.x * 8 + (threadIdx.x >> 5);
    int lane = threadIdx.x & 31;
    int src = __ldg(&ei[e]);
    int dst = __ldg(&ei[Ec + e]);
    int r   = __ldg(&et[e]);
    float s = __ldg(&inv[dst * Rc + r]);
    float4 v = *(const float4*)&h[(size_t)src * Hc + lane * 4];
    float* p = &agg[(size_t)dst * (Rc * Hc) + r * Hc + lane * 4];
    asm volatile("red.global.add.v4.f32 [%0], {%1,%2,%3,%4};"
                 :: "l"(p), "f"(v.x * s), "f"(v.y * s), "f"(v.z * s), "f"(v.w * s)
                 : "memory");
}

// ---------------- fused GEMM: out = act( A1@B1 + A2@B2 + bias ) ----------------
// BM=64 rows, BN=128 cols (full H), BK=16. 256 threads.
// thread grid: 8 warps (row groups of 8) x 32 lanes (col groups of 4).
// Each warp owns 8 full rows -> LN is a pure warp-shuffle reduction.
#define BM 64
#define BN 128
#define BK 16

template<bool DO_LN>
__global__ void __launch_bounds__(256) gemm_fused(
    const float* __restrict__ A1, int lda1, int K1, const float* __restrict__ B1,
    const float* __restrict__ A2, int K2, const float* __restrict__ B2,
    const float* __restrict__ bias,
    const float* __restrict__ lng, const float* __restrict__ lnb,
    float* __restrict__ out)
{
    __shared__ float As[BK][BM + 4];
    __shared__ float Bs[BK][BN];

    const int tid  = threadIdx.x;
    const int row0 = blockIdx.x * BM;
    const int tr = tid >> 5;    // warp id 0..7 -> rows tr*8 .. tr*8+7
    const int tc = tid & 31;    // lane      -> cols tc*4 .. tc*4+3

    float acc[8][4];
#pragma unroll
    for (int i = 0; i < 8; i++)
#pragma unroll
        for (int j = 0; j < 4; j++) acc[i][j] = 0.0f;

    const int ar = tid >> 2;            // 0..63 (A row within tile)
    const int ac = (tid & 3) << 2;      // 0,4,8,12 (A col within tile)
    const int br = tid >> 5;            // 0..7 (B row within tile)
    const int bc = (tid & 31) << 2;     // 0..124

#pragma unroll
    for (int seg = 0; seg < 2; seg++) {
        const float* A = seg ? A2 : A1;
        const float* B = seg ? B2 : B1;
        const int K   = seg ? K2 : K1;
        const int lda = seg ? K2 : lda1;
        if (K == 0) continue;
        for (int k0 = 0; k0 < K; k0 += BK) {
            float4 av = *(const float4*)&A[(size_t)(row0 + ar) * lda + k0 + ac];
            As[ac + 0][ar] = av.x;
            As[ac + 1][ar] = av.y;
            As[ac + 2][ar] = av.z;
            As[ac + 3][ar] = av.w;
            *(float4*)&Bs[br][bc]     = *(const float4*)&B[(size_t)(k0 + br) * BN + bc];
            *(float4*)&Bs[br + 8][bc] = *(const float4*)&B[(size_t)(k0 + br + 8) * BN + bc];
            __syncthreads();
#pragma unroll
            for (int k = 0; k < BK; k++) {
                float4 b = *(const float4*)&Bs[k][tc << 2];
                float4 a0 = *(const float4*)&As[k][tr << 3];
                float4 a1 = *(const float4*)&As[k][(tr << 3) + 4];
                float a[8] = {a0.x, a0.y, a0.z, a0.w, a1.x, a1.y, a1.z, a1.w};
#pragma unroll
                for (int i = 0; i < 8; i++) {
                    acc[i][0] += a[i] * b.x;
                    acc[i][1] += a[i] * b.y;
                    acc[i][2] += a[i] * b.z;
                    acc[i][3] += a[i] * b.w;
                }
            }
            __syncthreads();
        }
    }

    // epilogue
    const float inv128 = 1.0f / 128.0f;
    float4 bv = *(const float4*)&bias[tc << 2];
    float4 gv = {0, 0, 0, 0}, lbv = {0, 0, 0, 0};
    if (DO_LN) {
        gv  = *(const float4*)&lng[tc << 2];
        lbv = *(const float4*)&lnb[tc << 2];
    }
#pragma unroll
    for (int i = 0; i < 8; i++) {
        float x0 = acc[i][0] + bv.x;
        float x1 = acc[i][1] + bv.y;
        float x2 = acc[i][2] + bv.z;
        float x3 = acc[i][3] + bv.w;
        float4 o;
        if (DO_LN) {
            float s  = x0 + x1 + x2 + x3;
            float sq = x0 * x0 + x1 * x1 + x2 * x2 + x3 * x3;
#pragma unroll
            for (int off = 16; off; off >>= 1) {
                s  += __shfl_xor_sync(0xffffffffu, s, off);
                sq += __shfl_xor_sync(0xffffffffu, sq, off);
            }
            float mu  = s * inv128;
            float var = sq * inv128 - mu * mu;
            float rs  = rsqrtf(var + 1e-5f);
            o.x = fmaxf((x0 - mu) * rs * gv.x + lbv.x, 0.0f);
            o.y = fmaxf((x1 - mu) * rs * gv.y + lbv.y, 0.0f);
            o.z = fmaxf((x2 - mu) * rs * gv.z + lbv.z, 0.0f);
            o.w = fmaxf((x3 - mu) * rs * gv.w + lbv.w, 0.0f);
        } else {
            o.x = fmaxf(x0, 0.0f);
            o.y = fmaxf(x1, 0.0f);
            o.z = fmaxf(x2, 0.0f);
            o.w = fmaxf(x3, 0.0f);
        }
        *(float4*)&out[(size_t)(row0 + (tr << 3) + i) * Hc + (tc << 2)] = o;
    }
}

// ---------------- output head: pred = base + h[:NA] @ W_out + b_out ----------------
__global__ void __launch_bounds__(256) out_kernel(
    const float* __restrict__ h, const float* __restrict__ Wout,
    const float* __restrict__ bout, const float* __restrict__ basep,
    float* __restrict__ pred)
{
    int warp = threadIdx.x >> 5;
    int lane = threadIdx.x & 31;
    int row = blockIdx.x * 8 + warp;
    float4 hv = *(const float4*)&h[(size_t)row * Hc + lane * 4];
    float4 wv = *(const float4*)&Wout[lane * 4];
    float s = hv.x * wv.x + hv.y * wv.y + hv.z * wv.z + hv.w * wv.w;
#pragma unroll
    for (int off = 16; off; off >>= 1) s += __shfl_xor_sync(0xffffffffu, s, off);
    if (lane == 0) pred[row] = basep[0] + s + bout[0];
}

// ---------------- launch ----------------
extern "C" void kernel_launch(void* const* d_in, const int* in_sizes, int n_in,
                              void* d_out, int out_size)
{
    const float* xa     = (const float*)d_in[0];
    const float* xw     = (const float*)d_in[1];
    const int*   ei     = (const int*)  d_in[2];
    const int*   et     = (const int*)  d_in[3];
    const float* W_in_a = (const float*)d_in[4];
    const float* b_in_a = (const float*)d_in[5];
    const float* W_in_w = (const float*)d_in[6];
    const float* b_in_w = (const float*)d_in[7];
    const float* W_rel  = (const float*)d_in[8];   // [2,4,128,128]
    const float* W_root = (const float*)d_in[9];   // [2,128,128]
    const float* b_conv = (const float*)d_in[10];  // [2,128]
    const float* ln_g   = (const float*)d_in[11];
    const float* ln_b   = (const float*)d_in[12];
    const float* W_out  = (const float*)d_in[13];
    const float* b_out  = (const float*)d_in[14];
    const float* base   = (const float*)d_in[15];
    float* pred = (float*)d_out;

    void *p_hA, *p_hB, *p_agg, *p_inv, *p_cnt;
    cudaGetSymbolAddress(&p_hA, g_hA);
    cudaGetSymbolAddress(&p_hB, g_hB);
    cudaGetSymbolAddress(&p_agg, g_agg);
    cudaGetSymbolAddress(&p_inv, g_inv);
    cudaGetSymbolAddress(&p_cnt, g_cnt);
    float* hA  = (float*)p_hA;
    float* hB  = (float*)p_hB;
    float* agg = (float*)p_agg;
    float* inv = (float*)p_inv;
    int*   cnt = (int*)p_cnt;

    // per-(node,type) in-degree counts (layer-invariant)
    cudaMemsetAsync(cnt, 0, (size_t)Nc * Rc * sizeof(int));
    count_kernel<<<Ec / 256, 256>>>(ei, et, cnt);
    inv_kernel<<<(Nc * Rc) / 256, 256>>>(cnt, inv);

    // input projections -> hA
    gemm_fused<false><<<NAc / BM, 256>>>(xa, 64, 64, W_in_a,
                                         nullptr, 0, nullptr,
                                         b_in_a, nullptr, nullptr, hA);
    gemm_fused<false><<<NWc / BM, 256>>>(xw, 64, 64, W_in_w,
                                         nullptr, 0, nullptr,
                                         b_in_w, nullptr, nullptr, hA + (size_t)NAc * Hc);

    float* hcur = hA;
    float* hnxt = hB;
    for (int l = 0; l < 2; l++) {
        cudaMemsetAsync(agg, 0, (size_t)Nc * Rc * Hc * sizeof(float));
        scatter_kernel<<<Ec / 8, 256>>>(hcur, ei, et, inv, agg);
        gemm_fused<true><<<Nc / BM, 256>>>(
            hcur, Hc, Hc, W_root + (size_t)l * Hc * Hc,
            agg, Rc * Hc, W_rel + (size_t)l * Rc * Hc * Hc,
            b_conv + l * Hc, ln_g + l * Hc, ln_b + l * Hc, hnxt);
        float* t = hcur; hcur = hnxt; hnxt = t;
    }

    out_kernel<<<NAc / 8, 256>>>(hcur, W_out, b_out, base, pred);
}

// round 2
// speedup vs baseline: 1.5027x; 1.5027x over previous
#include <cuda_runtime.h>
#include <cuda_bf16.h>
#include <cstdint>

#define NAc 131072
#define NWc 131072
#define Nc  262144
#define Ec  1048576
#define Hc  128
#define Rc  4

// ---------------- scratch (static __device__, no runtime alloc) ----------------
__device__ float g_hA[(size_t)Nc * Hc];           // 128 MB
__device__ float g_hB[(size_t)Nc * Hc];           // 128 MB
__device__ float g_agg[(size_t)Nc * Rc * Hc];     // 512 MB
__device__ float g_inv[(size_t)Nc * Rc];          // 4 MB
__device__ int   g_cnt[(size_t)Nc * Rc];          // 4 MB

// ---------------- edge-type counting ----------------
__global__ void count_kernel(const int* __restrict__ ei, const int* __restrict__ et,
                             int* __restrict__ cnt) {
    int e = blockIdx.x * blockDim.x + threadIdx.x;
    if (e < Ec) {
        int dst = ei[Ec + e];
        int r = et[e];
        atomicAdd(&cnt[dst * Rc + r], 1);
    }
}

__global__ void inv_kernel(const int* __restrict__ cnt, float* __restrict__ inv) {
    int i = blockIdx.x * blockDim.x + threadIdx.x;
    if (i < Nc * Rc) {
        int c = cnt[i];
        inv[i] = 1.0f / (float)(c > 0 ? c : 1);
    }
}

// ---------------- scatter: agg[dst][r] += h[src] * inv[dst][r] ----------------
__global__ void __launch_bounds__(256) scatter_kernel(
    const float* __restrict__ h, const int* __restrict__ ei,
    const int* __restrict__ et, const float* __restrict__ inv,
    float* __restrict__ agg)
{
    int e = blockIdx.x * 8 + (threadIdx.x >> 5);
    int lane = threadIdx.x & 31;
    int src = __ldg(&ei[e]);
    int dst = __ldg(&ei[Ec + e]);
    int r   = __ldg(&et[e]);
    float s = __ldg(&inv[dst * Rc + r]);
    float4 v = *(const float4*)&h[(size_t)src * Hc + lane * 4];
    float* p = &agg[(size_t)dst * (Rc * Hc) + r * Hc + lane * 4];
    asm volatile("red.global.add.v4.f32 [%0], {%1,%2,%3,%4};"
                 :: "l"(p), "f"(v.x * s), "f"(v.y * s), "f"(v.z * s), "f"(v.w * s)
                 : "memory");
}

// ---------------- input projection GEMM (fp32 FFMA, small) ----------------
#define BM 64
#define BN 128
#define BK 16

__global__ void __launch_bounds__(256) gemm_inproj(
    const float* __restrict__ A1, int lda1, int K1, const float* __restrict__ B1,
    const float* __restrict__ bias, float* __restrict__ out)
{
    __shared__ float As[BK][BM + 4];
    __shared__ float Bs[BK][BN];

    const int tid  = threadIdx.x;
    const int row0 = blockIdx.x * BM;
    const int tr = tid >> 5;
    const int tc = tid & 31;

    float acc[8][4];
#pragma unroll
    for (int i = 0; i < 8; i++)
#pragma unroll
        for (int j = 0; j < 4; j++) acc[i][j] = 0.0f;

    const int ar = tid >> 2;
    const int ac = (tid & 3) << 2;
    const int br = tid >> 5;
    const int bc = (tid & 31) << 2;

    for (int k0 = 0; k0 < K1; k0 += BK) {
        float4 av = *(const float4*)&A1[(size_t)(row0 + ar) * lda1 + k0 + ac];
        As[ac + 0][ar] = av.x;
        As[ac + 1][ar] = av.y;
        As[ac + 2][ar] = av.z;
        As[ac + 3][ar] = av.w;
        *(float4*)&Bs[br][bc]     = *(const float4*)&B1[(size_t)(k0 + br) * BN + bc];
        *(float4*)&Bs[br + 8][bc] = *(const float4*)&B1[(size_t)(k0 + br + 8) * BN + bc];
        __syncthreads();
#pragma unroll
        for (int k = 0; k < BK; k++) {
            float4 b = *(const float4*)&Bs[k][tc << 2];
            float4 a0 = *(const float4*)&As[k][tr << 3];
            float4 a1 = *(const float4*)&As[k][(tr << 3) + 4];
            float a[8] = {a0.x, a0.y, a0.z, a0.w, a1.x, a1.y, a1.z, a1.w};
#pragma unroll
            for (int i = 0; i < 8; i++) {
                acc[i][0] += a[i] * b.x;
                acc[i][1] += a[i] * b.y;
                acc[i][2] += a[i] * b.z;
                acc[i][3] += a[i] * b.w;
            }
        }
        __syncthreads();
    }

    float4 bv = *(const float4*)&bias[tc << 2];
#pragma unroll
    for (int i = 0; i < 8; i++) {
        float4 o;
        o.x = fmaxf(acc[i][0] + bv.x, 0.0f);
        o.y = fmaxf(acc[i][1] + bv.y, 0.0f);
        o.z = fmaxf(acc[i][2] + bv.z, 0.0f);
        o.w = fmaxf(acc[i][3] + bv.w, 0.0f);
        *(float4*)&out[(size_t)(row0 + (tr << 3) + i) * Hc + (tc << 2)] = o;
    }
}

// ---------------- conv GEMM: tf32 tensor cores + fused LN/ReLU ----------------
// out = relu(LN( h@W_root + agg@W_rel_stacked + bias ))
// BM=128, BN=128, BK=16; 256 threads = 8 warps as 4(M) x 2(N); warp tile 32x64.
#define CBM 128
#define CBN 128
#define CBK 16
#define CPAD 4
#define CLDA (CBM + CPAD)
#define CLDB (CBN + CPAD)

__device__ __forceinline__ uint32_t f2tf(float f) {
    uint32_t u;
    asm("cvt.rna.tf32.f32 %0, %1;" : "=r"(u) : "f"(f));
    return u;
}

__device__ __forceinline__ void mma_tf32(float c[4], const uint32_t a[4], const uint32_t b[2]) {
    asm volatile(
        "mma.sync.aligned.m16n8k8.row.col.f32.tf32.tf32.f32 "
        "{%0,%1,%2,%3}, {%4,%5,%6,%7}, {%8,%9}, {%0,%1,%2,%3};"
        : "+f"(c[0]), "+f"(c[1]), "+f"(c[2]), "+f"(c[3])
        : "r"(a[0]), "r"(a[1]), "r"(a[2]), "r"(a[3]), "r"(b[0]), "r"(b[1]));
}

extern __shared__ float conv_smem[];

__global__ void __launch_bounds__(256) conv_gemm_tf32(
    const float* __restrict__ A1, const float* __restrict__ B1,   // h, W_root [128,128]
    const float* __restrict__ A2, const float* __restrict__ B2,   // agg, W_rel [512,128]
    const float* __restrict__ bias,
    const float* __restrict__ lng, const float* __restrict__ lnb,
    float* __restrict__ out)
{
    uint32_t* As_u = (uint32_t*)conv_smem;              // [CBK][CLDA]
    uint32_t* Bs_u = As_u + CBK * CLDA;                 // [CBK][CLDB]

    const int tid  = threadIdx.x;
    const int lane = tid & 31;
    const int wid  = tid >> 5;
    const int warpM = wid >> 1;      // 0..3
    const int warpN = wid & 1;       // 0..1
    const int t = lane & 3;
    const int g = lane >> 2;
    const int m0 = warpM * 32;
    const int n0 = warpN * 64;
    const size_t row0 = (size_t)blockIdx.x * CBM;

    float acc[2][8][4];
#pragma unroll
    for (int mi = 0; mi < 2; mi++)
#pragma unroll
        for (int ni = 0; ni < 8; ni++)
#pragma unroll
            for (int j = 0; j < 4; j++) acc[mi][ni][j] = 0.0f;

#pragma unroll
    for (int seg = 0; seg < 2; seg++) {
        const float* A = seg ? A2 : A1;
        const float* B = seg ? B2 : B1;
        const int K   = seg ? 512 : 128;
        const int lda = seg ? 512 : 128;
        for (int k0 = 0; k0 < K; k0 += CBK) {
            __syncthreads();
#pragma unroll
            for (int i = 0; i < 2; i++) {
                int id = tid + i * 256;                 // 0..511
                int arow = id >> 2;                     // 0..127
                int akc  = (id & 3) << 2;               // 0,4,8,12
                float4 av = *(const float4*)&A[(row0 + arow) * lda + k0 + akc];
                As_u[(akc + 0) * CLDA + arow] = f2tf(av.x);
                As_u[(akc + 1) * CLDA + arow] = f2tf(av.y);
                As_u[(akc + 2) * CLDA + arow] = f2tf(av.z);
                As_u[(akc + 3) * CLDA + arow] = f2tf(av.w);
                int brow = id >> 5;                     // 0..15
                int bcol = (id & 31) << 2;              // 0..124
                float4 bvv = *(const float4*)&B[(size_t)(k0 + brow) * CBN + bcol];
                uint4 bu;
                bu.x = f2tf(bvv.x); bu.y = f2tf(bvv.y);
                bu.z = f2tf(bvv.z); bu.w = f2tf(bvv.w);
                *(uint4*)&Bs_u[brow * CLDB + bcol] = bu;
            }
            __syncthreads();
#pragma unroll
            for (int kk = 0; kk < CBK; kk += 8) {
                uint32_t a[2][4];
#pragma unroll
                for (int mi = 0; mi < 2; mi++) {
                    int mr = m0 + mi * 16 + g;
                    a[mi][0] = As_u[(kk + t) * CLDA + mr];
                    a[mi][1] = As_u[(kk + t) * CLDA + mr + 8];
                    a[mi][2] = As_u[(kk + t + 4) * CLDA + mr];
                    a[mi][3] = As_u[(kk + t + 4) * CLDA + mr + 8];
                }
                uint32_t b[8][2];
#pragma unroll
                for (int ni = 0; ni < 8; ni++) {
                    int nc = n0 + ni * 8 + g;
                    b[ni][0] = Bs_u[(kk + t) * CLDB + nc];
                    b[ni][1] = Bs_u[(kk + t + 4) * CLDB + nc];
                }
#pragma unroll
                for (int mi = 0; mi < 2; mi++)
#pragma unroll
                    for (int ni = 0; ni < 8; ni++)
                        mma_tf32(acc[mi][ni], a[mi], b[ni]);
            }
        }
    }

    // ---- epilogue: dump C to smem tile, fused LN + ReLU ----
    __syncthreads();
    float* Cs = conv_smem;    // [CBM][CLDB]
#pragma unroll
    for (int mi = 0; mi < 2; mi++) {
        int r = m0 + mi * 16 + g;
#pragma unroll
        for (int ni = 0; ni < 8; ni++) {
            int cc = n0 + ni * 8 + 2 * t;
            Cs[r * CLDB + cc]           = acc[mi][ni][0];
            Cs[r * CLDB + cc + 1]       = acc[mi][ni][1];
            Cs[(r + 8) * CLDB + cc]     = acc[mi][ni][2];
            Cs[(r + 8) * CLDB + cc + 1] = acc[mi][ni][3];
        }
    }
    __syncthreads();

    const float inv128 = 1.0f / 128.0f;
    float4 bv  = *(const float4*)&bias[lane << 2];
    float4 gv  = *(const float4*)&lng[lane << 2];
    float4 lbv = *(const float4*)&lnb[lane << 2];
#pragma unroll
    for (int rr = 0; rr < 16; rr++) {
        int r = wid * 16 + rr;
        float4 x = *(float4*)&Cs[r * CLDB + (lane << 2)];
        x.x += bv.x; x.y += bv.y; x.z += bv.z; x.w += bv.w;
        float s  = x.x + x.y + x.z + x.w;
        float sq = x.x * x.x + x.y * x.y + x.z * x.z + x.w * x.w;
#pragma unroll
        for (int off = 16; off; off >>= 1) {
            s  += __shfl_xor_sync(0xffffffffu, s, off);
            sq += __shfl_xor_sync(0xffffffffu, sq, off);
        }
        float mu  = s * inv128;
        float var = sq * inv128 - mu * mu;
        float rs  = rsqrtf(var + 1e-5f);
        float4 o;
        o.x = fmaxf((x.x - mu) * rs * gv.x + lbv.x, 0.0f);
        o.y = fmaxf((x.y - mu) * rs * gv.y + lbv.y, 0.0f);
        o.z = fmaxf((x.z - mu) * rs * gv.z + lbv.z, 0.0f);
        o.w = fmaxf((x.w - mu) * rs * gv.w + lbv.w, 0.0f);
        *(float4*)&out[(row0 + r) * Hc + (lane << 2)] = o;
    }
}

// ---------------- output head ----------------
__global__ void __launch_bounds__(256) out_kernel(
    const float* __restrict__ h, const float* __restrict__ Wout,
    const float* __restrict__ bout, const float* __restrict__ basep,
    float* __restrict__ pred)
{
    int warp = threadIdx.x >> 5;
    int lane = threadIdx.x & 31;
    int row = blockIdx.x * 8 + warp;
    float4 hv = *(const float4*)&h[(size_t)row * Hc + lane * 4];
    float4 wv = *(const float4*)&Wout[lane * 4];
    float s = hv.x * wv.x + hv.y * wv.y + hv.z * wv.z + hv.w * wv.w;
#pragma unroll
    for (int off = 16; off; off >>= 1) s += __shfl_xor_sync(0xffffffffu, s, off);
    if (lane == 0) pred[row] = basep[0] + s + bout[0];
}

// ---------------- launch ----------------
extern "C" void kernel_launch(void* const* d_in, const int* in_sizes, int n_in,
                              void* d_out, int out_size)
{
    const float* xa     = (const float*)d_in[0];
    const float* xw     = (const float*)d_in[1];
    const int*   ei     = (const int*)  d_in[2];
    const int*   et     = (const int*)  d_in[3];
    const float* W_in_a = (const float*)d_in[4];
    const float* b_in_a = (const float*)d_in[5];
    const float* W_in_w = (const float*)d_in[6];
    const float* b_in_w = (const float*)d_in[7];
    const float* W_rel  = (const float*)d_in[8];   // [2,4,128,128]
    const float* W_root = (const float*)d_in[9];   // [2,128,128]
    const float* b_conv = (const float*)d_in[10];  // [2,128]
    const float* ln_g   = (const float*)d_in[11];
    const float* ln_b   = (const float*)d_in[12];
    const float* W_out  = (const float*)d_in[13];
    const float* b_out  = (const float*)d_in[14];
    const float* base   = (const float*)d_in[15];
    float* pred = (float*)d_out;

    void *p_hA, *p_hB, *p_agg, *p_inv, *p_cnt;
    cudaGetSymbolAddress(&p_hA, g_hA);
    cudaGetSymbolAddress(&p_hB, g_hB);
    cudaGetSymbolAddress(&p_agg, g_agg);
    cudaGetSymbolAddress(&p_inv, g_inv);
    cudaGetSymbolAddress(&p_cnt, g_cnt);
    float* hA  = (float*)p_hA;
    float* hB  = (float*)p_hB;
    float* agg = (float*)p_agg;
    float* inv = (float*)p_inv;
    int*   cnt = (int*)p_cnt;

    static bool attr_set = false;
    if (!attr_set) {
        cudaFuncSetAttribute(conv_gemm_tf32,
                             cudaFuncAttributeMaxDynamicSharedMemorySize,
                             CBM * CLDB * sizeof(float));
        attr_set = true;
    }
    const int conv_smem_bytes = CBM * CLDB * sizeof(float);   // 67.6 KB

    // per-(node,type) in-degree counts (layer-invariant)
    cudaMemsetAsync(cnt, 0, (size_t)Nc * Rc * sizeof(int));
    count_kernel<<<Ec / 256, 256>>>(ei, et, cnt);
    inv_kernel<<<(Nc * Rc) / 256, 256>>>(cnt, inv);

    // input projections -> hA
    gemm_inproj<<<NAc / BM, 256>>>(xa, 64, 64, W_in_a, b_in_a, hA);
    gemm_inproj<<<NWc / BM, 256>>>(xw, 64, 64, W_in_w, b_in_w, hA + (size_t)NAc * Hc);

    float* hcur = hA;
    float* hnxt = hB;
    for (int l = 0; l < 2; l++) {
        cudaMemsetAsync(agg, 0, (size_t)Nc * Rc * Hc * sizeof(float));
        scatter_kernel<<<Ec / 8, 256>>>(hcur, ei, et, inv, agg);
        conv_gemm_tf32<<<Nc / CBM, 256, conv_smem_bytes>>>(
            hcur, W_root + (size_t)l * Hc * Hc,
            agg,  W_rel  + (size_t)l * Rc * Hc * Hc,
            b_conv + l * Hc, ln_g + l * Hc, ln_b + l * Hc, hnxt);
        float* t = hcur; hcur = hnxt; hnxt = t;
    }

    out_kernel<<<NAc / 8, 256>>>(hcur, W_out, b_out, base, pred);
}

// round 3
// speedup vs baseline: 1.5469x; 1.0294x over previous
#include <cuda_runtime.h>
#include <cuda_bf16.h>
#include <cstdint>

#define NAc 131072
#define NWc 131072
#define Nc  262144
#define Ec  1048576
#define Hc  128
#define Rc  4

// ---------------- scratch (static __device__, no runtime alloc) ----------------
__device__ float g_hA[(size_t)Nc * Hc];           // 128 MB
__device__ float g_hB[(size_t)Nc * Hc];           // 128 MB
__device__ float g_agg[(size_t)Nc * Rc * Hc];     // 512 MB
__device__ float g_inv[(size_t)Nc * Rc];          // 4 MB
__device__ int   g_cnt[(size_t)Nc * Rc];          // 4 MB

// ---------------- edge-type counting ----------------
__global__ void count_kernel(const int* __restrict__ ei, const int* __restrict__ et,
                             int* __restrict__ cnt) {
    int e = blockIdx.x * blockDim.x + threadIdx.x;
    if (e < Ec) {
        int dst = ei[Ec + e];
        int r = et[e];
        atomicAdd(&cnt[dst * Rc + r], 1);
    }
}

__global__ void inv_kernel(const int* __restrict__ cnt, float* __restrict__ inv) {
    int i = blockIdx.x * blockDim.x + threadIdx.x;
    if (i < Nc * Rc) {
        int c = cnt[i];
        inv[i] = 1.0f / (float)(c > 0 ? c : 1);
    }
}

// ---------------- scatter: agg[dst][r] += h[src] * inv[dst][r] ----------------
__global__ void __launch_bounds__(256) scatter_kernel(
    const float* __restrict__ h, const int* __restrict__ ei,
    const int* __restrict__ et, const float* __restrict__ inv,
    float* __restrict__ agg)
{
    int e = blockIdx.x * 8 + (threadIdx.x >> 5);
    int lane = threadIdx.x & 31;
    int src = __ldg(&ei[e]);
    int dst = __ldg(&ei[Ec + e]);
    int r   = __ldg(&et[e]);
    float s = __ldg(&inv[dst * Rc + r]);
    float4 v = *(const float4*)&h[(size_t)src * Hc + lane * 4];
    float* p = &agg[(size_t)dst * (Rc * Hc) + r * Hc + lane * 4];
    asm volatile("red.global.add.v4.f32 [%0], {%1,%2,%3,%4};"
                 :: "l"(p), "f"(v.x * s), "f"(v.y * s), "f"(v.z * s), "f"(v.w * s)
                 : "memory");
}

// ---------------- input projection GEMM (fp32 FFMA, small) ----------------
#define BM 64
#define BN 128
#define BK 16

__global__ void __launch_bounds__(256) gemm_inproj(
    const float* __restrict__ A1, int lda1, int K1, const float* __restrict__ B1,
    const float* __restrict__ bias, float* __restrict__ out)
{
    __shared__ float As[BK][BM + 4];
    __shared__ float Bs[BK][BN];

    const int tid  = threadIdx.x;
    const int row0 = blockIdx.x * BM;
    const int tr = tid >> 5;
    const int tc = tid & 31;

    float acc[8][4];
#pragma unroll
    for (int i = 0; i < 8; i++)
#pragma unroll
        for (int j = 0; j < 4; j++) acc[i][j] = 0.0f;

    const int ar = tid >> 2;
    const int ac = (tid & 3) << 2;
    const int br = tid >> 5;
    const int bc = (tid & 31) << 2;

    for (int k0 = 0; k0 < K1; k0 += BK) {
        float4 av = *(const float4*)&A1[(size_t)(row0 + ar) * lda1 + k0 + ac];
        As[ac + 0][ar] = av.x;
        As[ac + 1][ar] = av.y;
        As[ac + 2][ar] = av.z;
        As[ac + 3][ar] = av.w;
        *(float4*)&Bs[br][bc]     = *(const float4*)&B1[(size_t)(k0 + br) * BN + bc];
        *(float4*)&Bs[br + 8][bc] = *(const float4*)&B1[(size_t)(k0 + br + 8) * BN + bc];
        __syncthreads();
#pragma unroll
        for (int k = 0; k < BK; k++) {
            float4 b = *(const float4*)&Bs[k][tc << 2];
            float4 a0 = *(const float4*)&As[k][tr << 3];
            float4 a1 = *(const float4*)&As[k][(tr << 3) + 4];
            float a[8] = {a0.x, a0.y, a0.z, a0.w, a1.x, a1.y, a1.z, a1.w};
#pragma unroll
            for (int i = 0; i < 8; i++) {
                acc[i][0] += a[i] * b.x;
                acc[i][1] += a[i] * b.y;
                acc[i][2] += a[i] * b.z;
                acc[i][3] += a[i] * b.w;
            }
        }
        __syncthreads();
    }

    float4 bv = *(const float4*)&bias[tc << 2];
#pragma unroll
    for (int i = 0; i < 8; i++) {
        float4 o;
        o.x = fmaxf(acc[i][0] + bv.x, 0.0f);
        o.y = fmaxf(acc[i][1] + bv.y, 0.0f);
        o.z = fmaxf(acc[i][2] + bv.z, 0.0f);
        o.w = fmaxf(acc[i][3] + bv.w, 0.0f);
        *(float4*)&out[(size_t)(row0 + (tr << 3) + i) * Hc + (tc << 2)] = o;
    }
}

// ---------------- conv GEMM: tf32 MMA + ldmatrix + double-buffer + fused LN/ReLU --
// out = relu(LN( h@W_root + agg@W_rel_stacked + bias ))
// Block tile 128x128, K=640 in 40 slabs of 16. 8 warps = 4(M)x2(N), warp 32x64.
// Smem rows use 80B stride (20 floats): conflict-free for STS.128 and ldmatrix.
#define CLDS   20          // floats per smem row (16 data + 4 pad)
#define CBUF   5120        // floats per staging buffer (As 2560 + Bs 2560)
#define NSLAB  40
#define CLDC   132         // epilogue C tile stride

__device__ __forceinline__ uint32_t f2tf(float f) {
    uint32_t u;
    asm("cvt.rna.tf32.f32 %0, %1;" : "=r"(u) : "f"(f));
    return u;
}

__device__ __forceinline__ void mma_tf32(float c[4], const uint32_t a[4], const uint32_t b[2]) {
    asm volatile(
        "mma.sync.aligned.m16n8k8.row.col.f32.tf32.tf32.f32 "
        "{%0,%1,%2,%3}, {%4,%5,%6,%7}, {%8,%9}, {%0,%1,%2,%3};"
        : "+f"(c[0]), "+f"(c[1]), "+f"(c[2]), "+f"(c[3])
        : "r"(a[0]), "r"(a[1]), "r"(a[2]), "r"(a[3]), "r"(b[0]), "r"(b[1]));
}

__device__ __forceinline__ void ldsm4(uint32_t& r0, uint32_t& r1, uint32_t& r2, uint32_t& r3,
                                      uint32_t addr) {
    asm volatile("ldmatrix.sync.aligned.m8n8.x4.shared.b16 {%0,%1,%2,%3}, [%4];"
                 : "=r"(r0), "=r"(r1), "=r"(r2), "=r"(r3) : "r"(addr));
}

extern __shared__ float conv_smem[];

__global__ void __launch_bounds__(256) conv_gemm_tf32(
    const float* __restrict__ A1, const float* __restrict__ B1,   // h, W_root [128,128]
    const float* __restrict__ A2, const float* __restrict__ B2,   // agg, W_rel [512,128]
    const float* __restrict__ bias,
    const float* __restrict__ lng, const float* __restrict__ lnb,
    float* __restrict__ out)
{
    const int tid  = threadIdx.x;
    const int lane = tid & 31;
    const int wid  = tid >> 5;
    const int m0 = (wid >> 1) * 32;
    const int n0 = (wid & 1) * 64;
    const size_t row0 = (size_t)blockIdx.x * 128;

    uint32_t smem_u;
    asm("{.reg .u64 t; cvta.to.shared.u64 t, %1; cvt.u32.u64 %0, t;}"
        : "=r"(smem_u) : "l"(conv_smem));

    // per-lane ldmatrix address offsets (bytes)
    const uint32_t aLane = ((lane & 7) + ((lane >> 3) & 1) * 8) * 80 + ((lane >> 4) & 1) * 16;
    const uint32_t bLane = ((lane & 7) + ((lane >> 4) & 1) * 8) * 80 + ((lane >> 3) & 1) * 16;

    // staging coordinates
    const int s_ar = tid >> 2;            // A row 0..63 (+64 on 2nd iter)
    const int s_ac = (tid & 3) << 2;      // A k-chunk 0,4,8,12
    const int s_bn = tid >> 1;            // B n 0..127
    const int s_bk = (tid & 1) << 3;      // B k base 0 or 8

    float acc[2][8][4];
#pragma unroll
    for (int mi = 0; mi < 2; mi++)
#pragma unroll
        for (int ni = 0; ni < 8; ni++)
#pragma unroll
            for (int j = 0; j < 4; j++) acc[mi][ni][j] = 0.0f;

    auto stage = [&](int s, int buf) {
        const float* A; const float* B; int k0; int lda;
        if (s < 8) { A = A1; lda = 128; k0 = s * 16;       B = B1 + k0 * 128; }
        else       { A = A2; lda = 512; k0 = (s - 8) * 16; B = B2 + (size_t)k0 * 128; }
        float* As = conv_smem + buf * CBUF;
        float* Bs = As + 2560;
#pragma unroll
        for (int i = 0; i < 2; i++) {
            int ar = s_ar + i * 64;
            float4 av = *(const float4*)&A[(row0 + ar) * (size_t)lda + k0 + s_ac];
            uint4 u;
            u.x = f2tf(av.x); u.y = f2tf(av.y); u.z = f2tf(av.z); u.w = f2tf(av.w);
            *(uint4*)((char*)As + ar * 80 + s_ac * 4) = u;
        }
        uint32_t bv[8];
#pragma unroll
        for (int j = 0; j < 8; j++) bv[j] = f2tf(B[(s_bk + j) * 128 + s_bn]);
        *(uint4*)((char*)Bs + s_bn * 80 + s_bk * 4)      = make_uint4(bv[0], bv[1], bv[2], bv[3]);
        *(uint4*)((char*)Bs + s_bn * 80 + s_bk * 4 + 16) = make_uint4(bv[4], bv[5], bv[6], bv[7]);
    };

    stage(0, 0);
    __syncthreads();

    for (int s = 0; s < NSLAB; s++) {
        int buf = s & 1;
        if (s + 1 < NSLAB) stage(s + 1, buf ^ 1);

        uint32_t Abase = smem_u + buf * (CBUF * 4);
        uint32_t Bbase = Abase + 2560 * 4;
#pragma unroll
        for (int kk = 0; kk < 16; kk += 8) {
            uint32_t a[2][4];
#pragma unroll
            for (int mi = 0; mi < 2; mi++)
                ldsm4(a[mi][0], a[mi][1], a[mi][2], a[mi][3],
                      Abase + (m0 + mi * 16) * 80 + kk * 4 + aLane);
            uint32_t b[8][2];
#pragma unroll
            for (int nip = 0; nip < 4; nip++)
                ldsm4(b[2 * nip][0], b[2 * nip][1], b[2 * nip + 1][0], b[2 * nip + 1][1],
                      Bbase + (n0 + nip * 16) * 80 + kk * 4 + bLane);
#pragma unroll
            for (int mi = 0; mi < 2; mi++)
#pragma unroll
                for (int ni = 0; ni < 8; ni++)
                    mma_tf32(acc[mi][ni], a[mi], b[ni]);
        }
        __syncthreads();
    }

    // ---- epilogue: dump C to smem tile, fused LN + ReLU ----
    float* Cs = conv_smem;    // [128][CLDC]
    const int t = lane & 3;
    const int g = lane >> 2;
#pragma unroll
    for (int mi = 0; mi < 2; mi++) {
        int r = m0 + mi * 16 + g;
#pragma unroll
        for (int ni = 0; ni < 8; ni++) {
            int cc = n0 + ni * 8 + 2 * t;
            Cs[r * CLDC + cc]           = acc[mi][ni][0];
            Cs[r * CLDC + cc + 1]       = acc[mi][ni][1];
            Cs[(r + 8) * CLDC + cc]     = acc[mi][ni][2];
            Cs[(r + 8) * CLDC + cc + 1] = acc[mi][ni][3];
        }
    }
    __syncthreads();

    const float inv128 = 1.0f / 128.0f;
    float4 bv  = *(const float4*)&bias[lane << 2];
    float4 gv  = *(const float4*)&lng[lane << 2];
    float4 lbv = *(const float4*)&lnb[lane << 2];
#pragma unroll
    for (int rr = 0; rr < 16; rr++) {
        int r = wid * 16 + rr;
        float4 x = *(float4*)&Cs[r * CLDC + (lane << 2)];
        x.x += bv.x; x.y += bv.y; x.z += bv.z; x.w += bv.w;
        float s  = x.x + x.y + x.z + x.w;
        float sq = x.x * x.x + x.y * x.y + x.z * x.z + x.w * x.w;
#pragma unroll
        for (int off = 16; off; off >>= 1) {
            s  += __shfl_xor_sync(0xffffffffu, s, off);
            sq += __shfl_xor_sync(0xffffffffu, sq, off);
        }
        float mu  = s * inv128;
        float var = sq * inv128 - mu * mu;
        float rs  = rsqrtf(var + 1e-5f);
        float4 o;
        o.x = fmaxf((x.x - mu) * rs * gv.x + lbv.x, 0.0f);
        o.y = fmaxf((x.y - mu) * rs * gv.y + lbv.y, 0.0f);
        o.z = fmaxf((x.z - mu) * rs * gv.z + lbv.z, 0.0f);
        o.w = fmaxf((x.w - mu) * rs * gv.w + lbv.w, 0.0f);
        *(float4*)&out[(row0 + r) * Hc + (lane << 2)] = o;
    }
}

// ---------------- output head ----------------
__global__ void __launch_bounds__(256) out_kernel(
    const float* __restrict__ h, const float* __restrict__ Wout,
    const float* __restrict__ bout, const float* __restrict__ basep,
    float* __restrict__ pred)
{
    int warp = threadIdx.x >> 5;
    int lane = threadIdx.x & 31;
    int row = blockIdx.x * 8 + warp;
    float4 hv = *(const float4*)&h[(size_t)row * Hc + lane * 4];
    float4 wv = *(const float4*)&Wout[lane * 4];
    float s = hv.x * wv.x + hv.y * wv.y + hv.z * wv.z + hv.w * wv.w;
#pragma unroll
    for (int off = 16; off; off >>= 1) s += __shfl_xor_sync(0xffffffffu, s, off);
    if (lane == 0) pred[row] = basep[0] + s + bout[0];
}

// ---------------- launch ----------------
extern "C" void kernel_launch(void* const* d_in, const int* in_sizes, int n_in,
                              void* d_out, int out_size)
{
    const float* xa     = (const float*)d_in[0];
    const float* xw     = (const float*)d_in[1];
    const int*   ei     = (const int*)  d_in[2];
    const int*   et     = (const int*)  d_in[3];
    const float* W_in_a = (const float*)d_in[4];
    const float* b_in_a = (const float*)d_in[5];
    const float* W_in_w = (const float*)d_in[6];
    const float* b_in_w = (const float*)d_in[7];
    const float* W_rel  = (const float*)d_in[8];   // [2,4,128,128]
    const float* W_root = (const float*)d_in[9];   // [2,128,128]
    const float* b_conv = (const float*)d_in[10];  // [2,128]
    const float* ln_g   = (const float*)d_in[11];
    const float* ln_b   = (const float*)d_in[12];
    const float* W_out  = (const float*)d_in[13];
    const float* b_out  = (const float*)d_in[14];
    const float* base   = (const float*)d_in[15];
    float* pred = (float*)d_out;

    void *p_hA, *p_hB, *p_agg, *p_inv, *p_cnt;
    cudaGetSymbolAddress(&p_hA, g_hA);
    cudaGetSymbolAddress(&p_hB, g_hB);
    cudaGetSymbolAddress(&p_agg, g_agg);
    cudaGetSymbolAddress(&p_inv, g_inv);
    cudaGetSymbolAddress(&p_cnt, g_cnt);
    float* hA  = (float*)p_hA;
    float* hB  = (float*)p_hB;
    float* agg = (float*)p_agg;
    float* inv = (float*)p_inv;
    int*   cnt = (int*)p_cnt;

    static bool attr_set = false;
    if (!attr_set) {
        cudaFuncSetAttribute(conv_gemm_tf32,
                             cudaFuncAttributeMaxDynamicSharedMemorySize,
                             128 * CLDC * sizeof(float));
        attr_set = true;
    }
    const int conv_smem_bytes = 128 * CLDC * sizeof(float);   // 67.6 KB

    // per-(node,type) in-degree counts (layer-invariant)
    cudaMemsetAsync(cnt, 0, (size_t)Nc * Rc * sizeof(int));
    count_kernel<<<Ec / 256, 256>>>(ei, et, cnt);
    inv_kernel<<<(Nc * Rc) / 256, 256>>>(cnt, inv);

    // input projections -> hA
    gemm_inproj<<<NAc / BM, 256>>>(xa, 64, 64, W_in_a, b_in_a, hA);
    gemm_inproj<<<NWc / BM, 256>>>(xw, 64, 64, W_in_w, b_in_w, hA + (size_t)NAc * Hc);

    float* hcur = hA;
    float* hnxt = hB;
    for (int l = 0; l < 2; l++) {
        cudaMemsetAsync(agg, 0, (size_t)Nc * Rc * Hc * sizeof(float));
        scatter_kernel<<<Ec / 8, 256>>>(hcur, ei, et, inv, agg);
        conv_gemm_tf32<<<Nc / 128, 256, conv_smem_bytes>>>(
            hcur, W_root + (size_t)l * Hc * Hc,
            agg,  W_rel  + (size_t)l * Rc * Hc * Hc,
            b_conv + l * Hc, ln_g + l * Hc, ln_b + l * Hc, hnxt);
        float* t = hcur; hcur = hnxt; hnxt = t;
    }

    out_kernel<<<NAc / 8, 256>>>(hcur, W_out, b_out, base, pred);
}

// round 4
// speedup vs baseline: 1.8127x; 1.1719x over previous
#include <cuda_runtime.h>
#include <cuda_bf16.h>
#include <cstdint>

#define NAc 131072
#define NWc 131072
#define Nc  262144
#define Ec  1048576
#define Hc  128
#define Rc  4
#define HTW 640                      // ht row width: [root | rel0..3]

// ---------------- scratch (static __device__, no runtime alloc) ----------------
__device__ float g_h0[(size_t)Nc * Hc];             // 128 MB
__device__ float g_h1[(size_t)Nc * Hc];             // 128 MB
__device__ float g_ht[(size_t)Nc * HTW];            // 640 MB
__device__ float g_inv[(size_t)Nc * Rc];            // 4 MB
__device__ int   g_cnt[(size_t)Nc * Rc];            // 4 MB
__device__ int   g_off[Nc + 1];
__device__ int   g_cur[Nc];
__device__ int   g_elist[Ec];
__device__ int   g_bsum[256];

// ---------------- histogram ----------------
__global__ void count_kernel(const int* __restrict__ ei, const int* __restrict__ et,
                             int* __restrict__ cnt) {
    int e = blockIdx.x * blockDim.x + threadIdx.x;
    if (e < Ec) {
        int dst = ei[Ec + e];
        int r = et[e];
        atomicAdd(&cnt[dst * Rc + r], 1);
    }
}

// ---------------- scan stage 1: per-1024-node blocks ----------------
__global__ void __launch_bounds__(256) scan1_kernel(
    const int* __restrict__ cnt, float* __restrict__ inv,
    int* __restrict__ off, int* __restrict__ bsum)
{
    __shared__ int sh[256];
    const int blk = blockIdx.x, tid = threadIdx.x;
    const int base = blk * 1024 + tid * 4;
    int d[4], tot = 0;
#pragma unroll
    for (int j = 0; j < 4; j++) {
        int node = base + j;
        int s = 0;
#pragma unroll
        for (int r = 0; r < 4; r++) {
            int c = cnt[node * 4 + r];
            inv[node * 4 + r] = 1.0f / (float)(c > 0 ? c : 1);
            s += c;
        }
        d[j] = s; tot += s;
    }
    sh[tid] = tot;
    __syncthreads();
    for (int o = 1; o < 256; o <<= 1) {
        int t = (tid >= o) ? sh[tid - o] : 0;
        __syncthreads();
        sh[tid] += t;
        __syncthreads();
    }
    int excl = sh[tid] - tot;
#pragma unroll
    for (int j = 0; j < 4; j++) { off[base + j] = excl; excl += d[j]; }
    if (tid == 255) bsum[blk] = sh[255];
}

// ---------------- scan stage 2: scan the 256 block sums ----------------
__global__ void __launch_bounds__(256) scan2_kernel(int* __restrict__ bsum) {
    __shared__ int sh[256];
    int tid = threadIdx.x;
    int v = bsum[tid];
    sh[tid] = v;
    __syncthreads();
    for (int o = 1; o < 256; o <<= 1) {
        int t = (tid >= o) ? sh[tid - o] : 0;
        __syncthreads();
        sh[tid] += t;
        __syncthreads();
    }
    bsum[tid] = sh[tid] - v;   // exclusive
}

// ---------------- scan stage 3: add block offsets, init cursors ----------------
__global__ void scan3_kernel(int* __restrict__ off, const int* __restrict__ bsum,
                             int* __restrict__ cur) {
    int i = blockIdx.x * blockDim.x + threadIdx.x;
    if (i < Nc) {
        int v = off[i] + bsum[i >> 10];
        off[i] = v;
        cur[i] = v;
        if (i == 0) off[Nc] = Ec;
    }
}

// ---------------- CSR fill ----------------
__global__ void fill_kernel(const int* __restrict__ ei, const int* __restrict__ et,
                            int* __restrict__ cur, int* __restrict__ elist) {
    int e = blockIdx.x * blockDim.x + threadIdx.x;
    if (e < Ec) {
        int src = ei[e];
        int dst = ei[Ec + e];
        int r = et[e];
        int pos = atomicAdd(&cur[dst], 1);
        elist[pos] = (src << 2) | r;
    }
}

// ---------------- input projection GEMM (fp32 FFMA, small) ----------------
#define BM 64
#define BN 128
#define BK 16

__global__ void __launch_bounds__(256) gemm_inproj(
    const float* __restrict__ A1, int lda1, int K1, const float* __restrict__ B1,
    const float* __restrict__ bias, float* __restrict__ out)
{
    __shared__ float As[BK][BM + 4];
    __shared__ float Bs[BK][BN];

    const int tid  = threadIdx.x;
    const int row0 = blockIdx.x * BM;
    const int tr = tid >> 5;
    const int tc = tid & 31;

    float acc[8][4];
#pragma unroll
    for (int i = 0; i < 8; i++)
#pragma unroll
        for (int j = 0; j < 4; j++) acc[i][j] = 0.0f;

    const int ar = tid >> 2;
    const int ac = (tid & 3) << 2;
    const int br = tid >> 5;
    const int bc = (tid & 31) << 2;

    for (int k0 = 0; k0 < K1; k0 += BK) {
        float4 av = *(const float4*)&A1[(size_t)(row0 + ar) * lda1 + k0 + ac];
        As[ac + 0][ar] = av.x;
        As[ac + 1][ar] = av.y;
        As[ac + 2][ar] = av.z;
        As[ac + 3][ar] = av.w;
        *(float4*)&Bs[br][bc]     = *(const float4*)&B1[(size_t)(k0 + br) * BN + bc];
        *(float4*)&Bs[br + 8][bc] = *(const float4*)&B1[(size_t)(k0 + br + 8) * BN + bc];
        __syncthreads();
#pragma unroll
        for (int k = 0; k < BK; k++) {
            float4 b = *(const float4*)&Bs[k][tc << 2];
            float4 a0 = *(const float4*)&As[k][tr << 3];
            float4 a1 = *(const float4*)&As[k][(tr << 3) + 4];
            float a[8] = {a0.x, a0.y, a0.z, a0.w, a1.x, a1.y, a1.z, a1.w};
#pragma unroll
            for (int i = 0; i < 8; i++) {
                acc[i][0] += a[i] * b.x;
                acc[i][1] += a[i] * b.y;
                acc[i][2] += a[i] * b.z;
                acc[i][3] += a[i] * b.w;
            }
        }
        __syncthreads();
    }

    float4 bv = *(const float4*)&bias[tc << 2];
#pragma unroll
    for (int i = 0; i < 8; i++) {
        float4 o;
        o.x = fmaxf(acc[i][0] + bv.x, 0.0f);
        o.y = fmaxf(acc[i][1] + bv.y, 0.0f);
        o.z = fmaxf(acc[i][2] + bv.z, 0.0f);
        o.w = fmaxf(acc[i][3] + bv.w, 0.0f);
        *(float4*)&out[(size_t)(row0 + (tr << 3) + i) * Hc + (tc << 2)] = o;
    }
}

// ---------------- ht GEMM: ht[:, cb*128:(cb+1)*128] = h @ Bsel (+bias if cb==0) ----
// tf32 MMA + ldmatrix + double-buffered staging. K=128 (8 slabs of 16).
#define CBUF   5120
#define CLDC   132

__device__ __forceinline__ uint32_t f2tf(float f) {
    uint32_t u;
    asm("cvt.rna.tf32.f32 %0, %1;" : "=r"(u) : "f"(f));
    return u;
}

__device__ __forceinline__ void mma_tf32(float c[4], const uint32_t a[4], const uint32_t b[2]) {
    asm volatile(
        "mma.sync.aligned.m16n8k8.row.col.f32.tf32.tf32.f32 "
        "{%0,%1,%2,%3}, {%4,%5,%6,%7}, {%8,%9}, {%0,%1,%2,%3};"
        : "+f"(c[0]), "+f"(c[1]), "+f"(c[2]), "+f"(c[3])
        : "r"(a[0]), "r"(a[1]), "r"(a[2]), "r"(a[3]), "r"(b[0]), "r"(b[1]));
}

__device__ __forceinline__ void ldsm4(uint32_t& r0, uint32_t& r1, uint32_t& r2, uint32_t& r3,
                                      uint32_t addr) {
    asm volatile("ldmatrix.sync.aligned.m8n8.x4.shared.b16 {%0,%1,%2,%3}, [%4];"
                 : "=r"(r0), "=r"(r1), "=r"(r2), "=r"(r3) : "r"(addr));
}

extern __shared__ float dyn_smem[];

__global__ void __launch_bounds__(256) ht_gemm(
    const float* __restrict__ A,        // h [N,128]
    const float* __restrict__ W_root,   // layer's [128,128]
    const float* __restrict__ W_rel,    // layer's [4,128,128]
    const float* __restrict__ bias,     // layer's [128]
    float* __restrict__ ht)
{
    const int cb = blockIdx.x;                 // column block 0..4
    const float* B = (cb == 0) ? W_root : (W_rel + (size_t)(cb - 1) * Hc * Hc);
    const size_t row0 = (size_t)blockIdx.y * 128;

    const int tid  = threadIdx.x;
    const int lane = tid & 31;
    const int wid  = tid >> 5;
    const int m0 = (wid >> 1) * 32;
    const int n0 = (wid & 1) * 64;

    uint32_t smem_u;
    asm("{.reg .u64 t; cvta.to.shared.u64 t, %1; cvt.u32.u64 %0, t;}"
        : "=r"(smem_u) : "l"(dyn_smem));

    const uint32_t aLane = ((lane & 7) + ((lane >> 3) & 1) * 8) * 80 + ((lane >> 4) & 1) * 16;
    const uint32_t bLane = ((lane & 7) + ((lane >> 4) & 1) * 8) * 80 + ((lane >> 3) & 1) * 16;

    const int s_ar = tid >> 2;
    const int s_ac = (tid & 3) << 2;
    const int s_bn = tid >> 1;
    const int s_bk = (tid & 1) << 3;

    float acc[2][8][4];
#pragma unroll
    for (int mi = 0; mi < 2; mi++)
#pragma unroll
        for (int ni = 0; ni < 8; ni++)
#pragma unroll
            for (int j = 0; j < 4; j++) acc[mi][ni][j] = 0.0f;

    auto stage = [&](int s, int buf) {
        int k0 = s * 16;
        float* As = dyn_smem + buf * CBUF;
        float* Bs = As + 2560;
#pragma unroll
        for (int i = 0; i < 2; i++) {
            int ar = s_ar + i * 64;
            float4 av = *(const float4*)&A[(row0 + ar) * (size_t)Hc + k0 + s_ac];
            uint4 u;
            u.x = f2tf(av.x); u.y = f2tf(av.y); u.z = f2tf(av.z); u.w = f2tf(av.w);
            *(uint4*)((char*)As + ar * 80 + s_ac * 4) = u;
        }
        uint32_t bv[8];
#pragma unroll
        for (int j = 0; j < 8; j++) bv[j] = f2tf(B[(size_t)(k0 + s_bk + j) * Hc + s_bn]);
        *(uint4*)((char*)Bs + s_bn * 80 + s_bk * 4)      = make_uint4(bv[0], bv[1], bv[2], bv[3]);
        *(uint4*)((char*)Bs + s_bn * 80 + s_bk * 4 + 16) = make_uint4(bv[4], bv[5], bv[6], bv[7]);
    };

    stage(0, 0);
    __syncthreads();

    for (int s = 0; s < 8; s++) {
        int buf = s & 1;
        if (s + 1 < 8) stage(s + 1, buf ^ 1);

        uint32_t Abase = smem_u + buf * (CBUF * 4);
        uint32_t Bbase = Abase + 2560 * 4;
#pragma unroll
        for (int kk = 0; kk < 16; kk += 8) {
            uint32_t a[2][4];
#pragma unroll
            for (int mi = 0; mi < 2; mi++)
                ldsm4(a[mi][0], a[mi][1], a[mi][2], a[mi][3],
                      Abase + (m0 + mi * 16) * 80 + kk * 4 + aLane);
            uint32_t b[8][2];
#pragma unroll
            for (int nip = 0; nip < 4; nip++)
                ldsm4(b[2 * nip][0], b[2 * nip][1], b[2 * nip + 1][0], b[2 * nip + 1][1],
                      Bbase + (n0 + nip * 16) * 80 + kk * 4 + bLane);
#pragma unroll
            for (int mi = 0; mi < 2; mi++)
#pragma unroll
                for (int ni = 0; ni < 8; ni++)
                    mma_tf32(acc[mi][ni], a[mi], b[ni]);
        }
        __syncthreads();
    }

    // epilogue: via smem for coalesced float4 stores
    float* Cs = dyn_smem;
    const int t = lane & 3;
    const int g = lane >> 2;
#pragma unroll
    for (int mi = 0; mi < 2; mi++) {
        int r = m0 + mi * 16 + g;
#pragma unroll
        for (int ni = 0; ni < 8; ni++) {
            int cc = n0 + ni * 8 + 2 * t;
            Cs[r * CLDC + cc]           = acc[mi][ni][0];
            Cs[r * CLDC + cc + 1]       = acc[mi][ni][1];
            Cs[(r + 8) * CLDC + cc]     = acc[mi][ni][2];
            Cs[(r + 8) * CLDC + cc + 1] = acc[mi][ni][3];
        }
    }
    __syncthreads();

    float4 bv = make_float4(0.f, 0.f, 0.f, 0.f);
    if (cb == 0) bv = *(const float4*)&bias[lane << 2];
#pragma unroll
    for (int rr = 0; rr < 16; rr++) {
        int r = wid * 16 + rr;
        float4 x = *(float4*)&Cs[r * CLDC + (lane << 2)];
        x.x += bv.x; x.y += bv.y; x.z += bv.z; x.w += bv.w;
        *(float4*)&ht[(row0 + r) * HTW + cb * Hc + (lane << 2)] = x;
    }
}

// ---------------- gather + LN + ReLU: one warp per destination node ----------------
__global__ void __launch_bounds__(256) gather_ln_kernel(
    const float* __restrict__ ht, const int* __restrict__ off,
    const int* __restrict__ elist, const float* __restrict__ inv,
    const float* __restrict__ lng, const float* __restrict__ lnb,
    float* __restrict__ out)
{
    const int warp = threadIdx.x >> 5;
    const int lane = threadIdx.x & 31;
    const int d = blockIdx.x * 8 + warp;

    float4 acc = *(const float4*)&ht[(size_t)d * HTW + (lane << 2)];   // root part
    const float4 iv = *(const float4*)&inv[d * 4];
    const int e0 = __ldg(&off[d]);
    const int e1 = __ldg(&off[d + 1]);

    for (int e = e0; e < e1; e++) {
        int p = __ldg(&elist[e]);
        int src = p >> 2;
        int r = p & 3;
        float s = (r & 1) ? ((r & 2) ? iv.w : iv.y) : ((r & 2) ? iv.z : iv.x);
        float4 v = *(const float4*)&ht[(size_t)src * HTW + (1 + r) * Hc + (lane << 2)];
        acc.x += s * v.x; acc.y += s * v.y; acc.z += s * v.z; acc.w += s * v.w;
    }

    // LayerNorm over the 128-wide row held by this warp
    float sum = acc.x + acc.y + acc.z + acc.w;
    float sq  = acc.x * acc.x + acc.y * acc.y + acc.z * acc.z + acc.w * acc.w;
#pragma unroll
    for (int o = 16; o; o >>= 1) {
        sum += __shfl_xor_sync(0xffffffffu, sum, o);
        sq  += __shfl_xor_sync(0xffffffffu, sq, o);
    }
    const float inv128 = 1.0f / 128.0f;
    float mu  = sum * inv128;
    float var = sq * inv128 - mu * mu;
    float rs  = rsqrtf(var + 1e-5f);
    float4 gv  = *(const float4*)&lng[lane << 2];
    float4 lbv = *(const float4*)&lnb[lane << 2];
    float4 o;
    o.x = fmaxf((acc.x - mu) * rs * gv.x + lbv.x, 0.0f);
    o.y = fmaxf((acc.y - mu) * rs * gv.y + lbv.y, 0.0f);
    o.z = fmaxf((acc.z - mu) * rs * gv.z + lbv.z, 0.0f);
    o.w = fmaxf((acc.w - mu) * rs * gv.w + lbv.w, 0.0f);
    *(float4*)&out[(size_t)d * Hc + (lane << 2)] = o;
}

// ---------------- output head ----------------
__global__ void __launch_bounds__(256) out_kernel(
    const float* __restrict__ h, const float* __restrict__ Wout,
    const float* __restrict__ bout, const float* __restrict__ basep,
    float* __restrict__ pred)
{
    int warp = threadIdx.x >> 5;
    int lane = threadIdx.x & 31;
    int row = blockIdx.x * 8 + warp;
    float4 hv = *(const float4*)&h[(size_t)row * Hc + lane * 4];
    float4 wv = *(const float4*)&Wout[lane * 4];
    float s = hv.x * wv.x + hv.y * wv.y + hv.z * wv.z + hv.w * wv.w;
#pragma unroll
    for (int off = 16; off; off >>= 1) s += __shfl_xor_sync(0xffffffffu, s, off);
    if (lane == 0) pred[row] = basep[0] + s + bout[0];
}

// ---------------- launch ----------------
extern "C" void kernel_launch(void* const* d_in, const int* in_sizes, int n_in,
                              void* d_out, int out_size)
{
    const float* xa     = (const float*)d_in[0];
    const float* xw     = (const float*)d_in[1];
    const int*   ei     = (const int*)  d_in[2];
    const int*   et     = (const int*)  d_in[3];
    const float* W_in_a = (const float*)d_in[4];
    const float* b_in_a = (const float*)d_in[5];
    const float* W_in_w = (const float*)d_in[6];
    const float* b_in_w = (const float*)d_in[7];
    const float* W_rel  = (const float*)d_in[8];   // [2,4,128,128]
    const float* W_root = (const float*)d_in[9];   // [2,128,128]
    const float* b_conv = (const float*)d_in[10];  // [2,128]
    const float* ln_g   = (const float*)d_in[11];
    const float* ln_b   = (const float*)d_in[12];
    const float* W_out  = (const float*)d_in[13];
    const float* b_out  = (const float*)d_in[14];
    const float* base   = (const float*)d_in[15];
    float* pred = (float*)d_out;

    void *p_h0, *p_h1, *p_ht, *p_inv, *p_cnt, *p_off, *p_cur, *p_elist, *p_bsum;
    cudaGetSymbolAddress(&p_h0, g_h0);
    cudaGetSymbolAddress(&p_h1, g_h1);
    cudaGetSymbolAddress(&p_ht, g_ht);
    cudaGetSymbolAddress(&p_inv, g_inv);
    cudaGetSymbolAddress(&p_cnt, g_cnt);
    cudaGetSymbolAddress(&p_off, g_off);
    cudaGetSymbolAddress(&p_cur, g_cur);
    cudaGetSymbolAddress(&p_elist, g_elist);
    cudaGetSymbolAddress(&p_bsum, g_bsum);
    float* h0  = (float*)p_h0;
    float* h1  = (float*)p_h1;
    float* ht  = (float*)p_ht;
    float* inv = (float*)p_inv;
    int* cnt   = (int*)p_cnt;
    int* off   = (int*)p_off;
    int* cur   = (int*)p_cur;
    int* elist = (int*)p_elist;
    int* bsum  = (int*)p_bsum;

    static bool attr_set = false;
    if (!attr_set) {
        cudaFuncSetAttribute(ht_gemm,
                             cudaFuncAttributeMaxDynamicSharedMemorySize,
                             128 * CLDC * sizeof(float));
        attr_set = true;
    }
    const int gemm_smem = 128 * CLDC * sizeof(float);   // 67.6 KB

    // ---- CSR build (once per call; reused by both layers) ----
    cudaMemsetAsync(cnt, 0, (size_t)Nc * Rc * sizeof(int));
    count_kernel<<<Ec / 256, 256>>>(ei, et, cnt);
    scan1_kernel<<<256, 256>>>(cnt, inv, off, bsum);
    scan2_kernel<<<1, 256>>>(bsum);
    scan3_kernel<<<Nc / 256, 256>>>(off, bsum, cur);
    fill_kernel<<<Ec / 256, 256>>>(ei, et, cur, elist);

    // ---- input projections -> h0 ----
    gemm_inproj<<<NAc / BM, 256>>>(xa, 64, 64, W_in_a, b_in_a, h0);
    gemm_inproj<<<NWc / BM, 256>>>(xw, 64, 64, W_in_w, b_in_w, h0 + (size_t)NAc * Hc);

    float* hcur = h0;
    float* hnxt = h1;
    for (int l = 0; l < 2; l++) {
        ht_gemm<<<dim3(5, Nc / 128), 256, gemm_smem>>>(
            hcur,
            W_root + (size_t)l * Hc * Hc,
            W_rel  + (size_t)l * Rc * Hc * Hc,
            b_conv + l * Hc, ht);
        gather_ln_kernel<<<Nc / 8, 256>>>(ht, off, elist, inv,
                                          ln_g + l * Hc, ln_b + l * Hc, hnxt);
        float* t = hcur; hcur = hnxt; hnxt = t;
    }

    out_kernel<<<NAc / 8, 256>>>(hcur, W_out, b_out, base, pred);
}

// round 5
// speedup vs baseline: 2.1549x; 1.1887x over previous
#include <cuda_runtime.h>
#include <cuda_fp16.h>
#include <cuda_bf16.h>
#include <cstdint>

#define NAc 131072
#define NWc 131072
#define Nc  262144
#define Ec  1048576
#define Hc  128
#define Rc  4
#define HTW 640                      // ht row width: [root | rel0..3]

// ---------------- scratch (static __device__, no runtime alloc) ----------------
__device__ float  g_h0[(size_t)Nc * Hc];            // 128 MB
__device__ float  g_h1[(size_t)Nc * Hc];            // 128 MB
__device__ __half g_ht[(size_t)Nc * HTW];           // 320 MB
__device__ float  g_inv[(size_t)Nc * Rc];           // 4 MB
__device__ int    g_cnt[(size_t)Nc * Rc];           // 4 MB
__device__ int    g_off[Nc + 1];
__device__ int    g_cur[Nc];
__device__ int    g_elist[Ec];
__device__ int    g_bsum[256];

// ---------------- histogram ----------------
__global__ void count_kernel(const int* __restrict__ ei, const int* __restrict__ et,
                             int* __restrict__ cnt) {
    int e = blockIdx.x * blockDim.x + threadIdx.x;
    if (e < Ec) {
        int dst = ei[Ec + e];
        int r = et[e];
        atomicAdd(&cnt[dst * Rc + r], 1);
    }
}

// ---------------- scan stage 1 ----------------
__global__ void __launch_bounds__(256) scan1_kernel(
    const int* __restrict__ cnt, float* __restrict__ inv,
    int* __restrict__ off, int* __restrict__ bsum)
{
    __shared__ int sh[256];
    const int blk = blockIdx.x, tid = threadIdx.x;
    const int base = blk * 1024 + tid * 4;
    int d[4], tot = 0;
#pragma unroll
    for (int j = 0; j < 4; j++) {
        int node = base + j;
        int s = 0;
#pragma unroll
        for (int r = 0; r < 4; r++) {
            int c = cnt[node * 4 + r];
            inv[node * 4 + r] = 1.0f / (float)(c > 0 ? c : 1);
            s += c;
        }
        d[j] = s; tot += s;
    }
    sh[tid] = tot;
    __syncthreads();
    for (int o = 1; o < 256; o <<= 1) {
        int t = (tid >= o) ? sh[tid - o] : 0;
        __syncthreads();
        sh[tid] += t;
        __syncthreads();
    }
    int excl = sh[tid] - tot;
#pragma unroll
    for (int j = 0; j < 4; j++) { off[base + j] = excl; excl += d[j]; }
    if (tid == 255) bsum[blk] = sh[255];
}

// ---------------- scan stage 2 ----------------
__global__ void __launch_bounds__(256) scan2_kernel(int* __restrict__ bsum) {
    __shared__ int sh[256];
    int tid = threadIdx.x;
    int v = bsum[tid];
    sh[tid] = v;
    __syncthreads();
    for (int o = 1; o < 256; o <<= 1) {
        int t = (tid >= o) ? sh[tid - o] : 0;
        __syncthreads();
        sh[tid] += t;
        __syncthreads();
    }
    bsum[tid] = sh[tid] - v;   // exclusive
}

// ---------------- scan stage 3 ----------------
__global__ void scan3_kernel(int* __restrict__ off, const int* __restrict__ bsum,
                             int* __restrict__ cur) {
    int i = blockIdx.x * blockDim.x + threadIdx.x;
    if (i < Nc) {
        int v = off[i] + bsum[i >> 10];
        off[i] = v;
        cur[i] = v;
        if (i == 0) off[Nc] = Ec;
    }
}

// ---------------- CSR fill ----------------
__global__ void fill_kernel(const int* __restrict__ ei, const int* __restrict__ et,
                            int* __restrict__ cur, int* __restrict__ elist) {
    int e = blockIdx.x * blockDim.x + threadIdx.x;
    if (e < Ec) {
        int src = ei[e];
        int dst = ei[Ec + e];
        int r = et[e];
        int pos = atomicAdd(&cur[dst], 1);
        elist[pos] = (src << 2) | r;
    }
}

// ---------------- input projection GEMM (fp32 FFMA, small) ----------------
#define BM 64
#define BN 128
#define BK 16

__global__ void __launch_bounds__(256) gemm_inproj(
    const float* __restrict__ A1, int lda1, int K1, const float* __restrict__ B1,
    const float* __restrict__ bias, float* __restrict__ out)
{
    __shared__ float As[BK][BM + 4];
    __shared__ float Bs[BK][BN];

    const int tid  = threadIdx.x;
    const int row0 = blockIdx.x * BM;
    const int tr = tid >> 5;
    const int tc = tid & 31;

    float acc[8][4];
#pragma unroll
    for (int i = 0; i < 8; i++)
#pragma unroll
        for (int j = 0; j < 4; j++) acc[i][j] = 0.0f;

    const int ar = tid >> 2;
    const int ac = (tid & 3) << 2;
    const int br = tid >> 5;
    const int bc = (tid & 31) << 2;

    for (int k0 = 0; k0 < K1; k0 += BK) {
        float4 av = *(const float4*)&A1[(size_t)(row0 + ar) * lda1 + k0 + ac];
        As[ac + 0][ar] = av.x;
        As[ac + 1][ar] = av.y;
        As[ac + 2][ar] = av.z;
        As[ac + 3][ar] = av.w;
        *(float4*)&Bs[br][bc]     = *(const float4*)&B1[(size_t)(k0 + br) * BN + bc];
        *(float4*)&Bs[br + 8][bc] = *(const float4*)&B1[(size_t)(k0 + br + 8) * BN + bc];
        __syncthreads();
#pragma unroll
        for (int k = 0; k < BK; k++) {
            float4 b = *(const float4*)&Bs[k][tc << 2];
            float4 a0 = *(const float4*)&As[k][tr << 3];
            float4 a1 = *(const float4*)&As[k][(tr << 3) + 4];
            float a[8] = {a0.x, a0.y, a0.z, a0.w, a1.x, a1.y, a1.z, a1.w};
#pragma unroll
            for (int i = 0; i < 8; i++) {
                acc[i][0] += a[i] * b.x;
                acc[i][1] += a[i] * b.y;
                acc[i][2] += a[i] * b.z;
                acc[i][3] += a[i] * b.w;
            }
        }
        __syncthreads();
    }

    float4 bv = *(const float4*)&bias[tc << 2];
#pragma unroll
    for (int i = 0; i < 8; i++) {
        float4 o;
        o.x = fmaxf(acc[i][0] + bv.x, 0.0f);
        o.y = fmaxf(acc[i][1] + bv.y, 0.0f);
        o.z = fmaxf(acc[i][2] + bv.z, 0.0f);
        o.w = fmaxf(acc[i][3] + bv.w, 0.0f);
        *(float4*)&out[(size_t)(row0 + (tr << 3) + i) * Hc + (tc << 2)] = o;
    }
}

// ---------------- ht GEMM: ht[:, cb*128:(cb+1)*128] = h @ Bsel (+bias if cb==0) ----
#define CBUF   5120
#define CLDC   132

__device__ __forceinline__ uint32_t f2tf(float f) {
    uint32_t u;
    asm("cvt.rna.tf32.f32 %0, %1;" : "=r"(u) : "f"(f));
    return u;
}

__device__ __forceinline__ void mma_tf32(float c[4], const uint32_t a[4], const uint32_t b[2]) {
    asm volatile(
        "mma.sync.aligned.m16n8k8.row.col.f32.tf32.tf32.f32 "
        "{%0,%1,%2,%3}, {%4,%5,%6,%7}, {%8,%9}, {%0,%1,%2,%3};"
        : "+f"(c[0]), "+f"(c[1]), "+f"(c[2]), "+f"(c[3])
        : "r"(a[0]), "r"(a[1]), "r"(a[2]), "r"(a[3]), "r"(b[0]), "r"(b[1]));
}

__device__ __forceinline__ void ldsm4(uint32_t& r0, uint32_t& r1, uint32_t& r2, uint32_t& r3,
                                      uint32_t addr) {
    asm volatile("ldmatrix.sync.aligned.m8n8.x4.shared.b16 {%0,%1,%2,%3}, [%4];"
                 : "=r"(r0), "=r"(r1), "=r"(r2), "=r"(r3) : "r"(addr));
}

extern __shared__ float dyn_smem[];

__global__ void __launch_bounds__(256) ht_gemm(
    const float* __restrict__ A,        // h [N,128]
    const float* __restrict__ W_root,   // layer's [128,128]
    const float* __restrict__ W_rel,    // layer's [4,128,128]
    const float* __restrict__ bias,     // layer's [128]
    __half* __restrict__ ht)
{
    const int cb = blockIdx.x;                 // column block 0..4
    const float* B = (cb == 0) ? W_root : (W_rel + (size_t)(cb - 1) * Hc * Hc);
    const size_t row0 = (size_t)blockIdx.y * 128;

    const int tid  = threadIdx.x;
    const int lane = tid & 31;
    const int wid  = tid >> 5;
    const int m0 = (wid >> 1) * 32;
    const int n0 = (wid & 1) * 64;

    uint32_t smem_u;
    asm("{.reg .u64 t; cvta.to.shared.u64 t, %1; cvt.u32.u64 %0, t;}"
        : "=r"(smem_u) : "l"(dyn_smem));

    const uint32_t aLane = ((lane & 7) + ((lane >> 3) & 1) * 8) * 80 + ((lane >> 4) & 1) * 16;
    const uint32_t bLane = ((lane & 7) + ((lane >> 4) & 1) * 8) * 80 + ((lane >> 3) & 1) * 16;

    const int s_ar = tid >> 2;
    const int s_ac = (tid & 3) << 2;
    const int s_bn = tid >> 1;
    const int s_bk = (tid & 1) << 3;

    float acc[2][8][4];
#pragma unroll
    for (int mi = 0; mi < 2; mi++)
#pragma unroll
        for (int ni = 0; ni < 8; ni++)
#pragma unroll
            for (int j = 0; j < 4; j++) acc[mi][ni][j] = 0.0f;

    auto stage = [&](int s, int buf) {
        int k0 = s * 16;
        float* As = dyn_smem + buf * CBUF;
        float* Bs = As + 2560;
#pragma unroll
        for (int i = 0; i < 2; i++) {
            int ar = s_ar + i * 64;
            float4 av = *(const float4*)&A[(row0 + ar) * (size_t)Hc + k0 + s_ac];
            uint4 u;
            u.x = f2tf(av.x); u.y = f2tf(av.y); u.z = f2tf(av.z); u.w = f2tf(av.w);
            *(uint4*)((char*)As + ar * 80 + s_ac * 4) = u;
        }
        uint32_t bv[8];
#pragma unroll
        for (int j = 0; j < 8; j++) bv[j] = f2tf(B[(size_t)(k0 + s_bk + j) * Hc + s_bn]);
        *(uint4*)((char*)Bs + s_bn * 80 + s_bk * 4)      = make_uint4(bv[0], bv[1], bv[2], bv[3]);
        *(uint4*)((char*)Bs + s_bn * 80 + s_bk * 4 + 16) = make_uint4(bv[4], bv[5], bv[6], bv[7]);
    };

    stage(0, 0);
    __syncthreads();

    for (int s = 0; s < 8; s++) {
        int buf = s & 1;
        if (s + 1 < 8) stage(s + 1, buf ^ 1);

        uint32_t Abase = smem_u + buf * (CBUF * 4);
        uint32_t Bbase = Abase + 2560 * 4;
#pragma unroll
        for (int kk = 0; kk < 16; kk += 8) {
            uint32_t a[2][4];
#pragma unroll
            for (int mi = 0; mi < 2; mi++)
                ldsm4(a[mi][0], a[mi][1], a[mi][2], a[mi][3],
                      Abase + (m0 + mi * 16) * 80 + kk * 4 + aLane);
            uint32_t b[8][2];
#pragma unroll
            for (int nip = 0; nip < 4; nip++)
                ldsm4(b[2 * nip][0], b[2 * nip][1], b[2 * nip + 1][0], b[2 * nip + 1][1],
                      Bbase + (n0 + nip * 16) * 80 + kk * 4 + bLane);
#pragma unroll
            for (int mi = 0; mi < 2; mi++)
#pragma unroll
                for (int ni = 0; ni < 8; ni++)
                    mma_tf32(acc[mi][ni], a[mi], b[ni]);
        }
        __syncthreads();
    }

    // epilogue: via smem, then fp16 coalesced stores
    float* Cs = dyn_smem;
    const int t = lane & 3;
    const int g = lane >> 2;
#pragma unroll
    for (int mi = 0; mi < 2; mi++) {
        int r = m0 + mi * 16 + g;
#pragma unroll
        for (int ni = 0; ni < 8; ni++) {
            int cc = n0 + ni * 8 + 2 * t;
            Cs[r * CLDC + cc]           = acc[mi][ni][0];
            Cs[r * CLDC + cc + 1]       = acc[mi][ni][1];
            Cs[(r + 8) * CLDC + cc]     = acc[mi][ni][2];
            Cs[(r + 8) * CLDC + cc + 1] = acc[mi][ni][3];
        }
    }
    __syncthreads();

    float4 bv = make_float4(0.f, 0.f, 0.f, 0.f);
    if (cb == 0) bv = *(const float4*)&bias[lane << 2];
#pragma unroll
    for (int rr = 0; rr < 16; rr++) {
        int r = wid * 16 + rr;
        float4 x = *(float4*)&Cs[r * CLDC + (lane << 2)];
        x.x += bv.x; x.y += bv.y; x.z += bv.z; x.w += bv.w;
        __half2 p0 = __floats2half2_rn(x.x, x.y);
        __half2 p1 = __floats2half2_rn(x.z, x.w);
        uint2 u = make_uint2(*(uint32_t*)&p0, *(uint32_t*)&p1);
        *(uint2*)&ht[(row0 + r) * HTW + cb * Hc + (lane << 2)] = u;
    }
}

// ---------------- gather + LN + ReLU (+ optional fused output head) ----------------
// one warp per destination node; ht is fp16, accumulate fp32
template<bool HEAD>
__global__ void __launch_bounds__(256) gather_ln_kernel(
    const __half* __restrict__ ht, const int* __restrict__ off,
    const int* __restrict__ elist, const float* __restrict__ inv,
    const float* __restrict__ lng, const float* __restrict__ lnb,
    float* __restrict__ out,
    const float* __restrict__ Wout, const float* __restrict__ bout,
    const float* __restrict__ basep)
{
    const int warp = threadIdx.x >> 5;
    const int lane = threadIdx.x & 31;
    const int d = blockIdx.x * 8 + warp;

    // root slice init
    float4 acc;
    {
        uint2 v = *(const uint2*)&ht[(size_t)d * HTW + (lane << 2)];
        float2 f0 = __half22float2(*(__half2*)&v.x);
        float2 f1 = __half22float2(*(__half2*)&v.y);
        acc = make_float4(f0.x, f0.y, f1.x, f1.y);
    }
    const float4 iv = *(const float4*)&inv[d * 4];
    const int e0 = __ldg(&off[d]);
    const int e1 = __ldg(&off[d + 1]);

    int e = e0;
    for (; e + 1 < e1; e += 2) {
        int p0 = __ldg(&elist[e]);
        int p1 = __ldg(&elist[e + 1]);
        int s0 = p0 >> 2, r0 = p0 & 3;
        int s1 = p1 >> 2, r1 = p1 & 3;
        float c0 = (r0 & 1) ? ((r0 & 2) ? iv.w : iv.y) : ((r0 & 2) ? iv.z : iv.x);
        float c1 = (r1 & 1) ? ((r1 & 2) ? iv.w : iv.y) : ((r1 & 2) ? iv.z : iv.x);
        uint2 v0 = *(const uint2*)&ht[(size_t)s0 * HTW + (1 + r0) * Hc + (lane << 2)];
        uint2 v1 = *(const uint2*)&ht[(size_t)s1 * HTW + (1 + r1) * Hc + (lane << 2)];
        float2 a0 = __half22float2(*(__half2*)&v0.x);
        float2 a1 = __half22float2(*(__half2*)&v0.y);
        float2 b0 = __half22float2(*(__half2*)&v1.x);
        float2 b1 = __half22float2(*(__half2*)&v1.y);
        acc.x += c0 * a0.x + c1 * b0.x;
        acc.y += c0 * a0.y + c1 * b0.y;
        acc.z += c0 * a1.x + c1 * b1.x;
        acc.w += c0 * a1.y + c1 * b1.y;
    }
    if (e < e1) {
        int p = __ldg(&elist[e]);
        int src = p >> 2, r = p & 3;
        float s = (r & 1) ? ((r & 2) ? iv.w : iv.y) : ((r & 2) ? iv.z : iv.x);
        uint2 v = *(const uint2*)&ht[(size_t)src * HTW + (1 + r) * Hc + (lane << 2)];
        float2 f0 = __half22float2(*(__half2*)&v.x);
        float2 f1 = __half22float2(*(__half2*)&v.y);
        acc.x += s * f0.x; acc.y += s * f0.y;
        acc.z += s * f1.x; acc.w += s * f1.y;
    }

    // LayerNorm over the 128-wide row held by this warp
    float sum = acc.x + acc.y + acc.z + acc.w;
    float sq  = acc.x * acc.x + acc.y * acc.y + acc.z * acc.z + acc.w * acc.w;
#pragma unroll
    for (int o = 16; o; o >>= 1) {
        sum += __shfl_xor_sync(0xffffffffu, sum, o);
        sq  += __shfl_xor_sync(0xffffffffu, sq, o);
    }
    const float inv128 = 1.0f / 128.0f;
    float mu  = sum * inv128;
    float var = sq * inv128 - mu * mu;
    float rs  = rsqrtf(var + 1e-5f);
    float4 gv  = *(const float4*)&lng[lane << 2];
    float4 lbv = *(const float4*)&lnb[lane << 2];
    float4 o;
    o.x = fmaxf((acc.x - mu) * rs * gv.x + lbv.x, 0.0f);
    o.y = fmaxf((acc.y - mu) * rs * gv.y + lbv.y, 0.0f);
    o.z = fmaxf((acc.z - mu) * rs * gv.z + lbv.z, 0.0f);
    o.w = fmaxf((acc.w - mu) * rs * gv.w + lbv.w, 0.0f);

    if (HEAD) {
        float4 wv = *(const float4*)&Wout[lane << 2];
        float s = o.x * wv.x + o.y * wv.y + o.z * wv.z + o.w * wv.w;
#pragma unroll
        for (int of = 16; of; of >>= 1) s += __shfl_xor_sync(0xffffffffu, s, of);
        if (lane == 0) out[d] = basep[0] + s + bout[0];
    } else {
        *(float4*)&out[(size_t)d * Hc + (lane << 2)] = o;
    }
}

// ---------------- launch ----------------
extern "C" void kernel_launch(void* const* d_in, const int* in_sizes, int n_in,
                              void* d_out, int out_size)
{
    const float* xa     = (const float*)d_in[0];
    const float* xw     = (const float*)d_in[1];
    const int*   ei     = (const int*)  d_in[2];
    const int*   et     = (const int*)  d_in[3];
    const float* W_in_a = (const float*)d_in[4];
    const float* b_in_a = (const float*)d_in[5];
    const float* W_in_w = (const float*)d_in[6];
    const float* b_in_w = (const float*)d_in[7];
    const float* W_rel  = (const float*)d_in[8];   // [2,4,128,128]
    const float* W_root = (const float*)d_in[9];   // [2,128,128]
    const float* b_conv = (const float*)d_in[10];  // [2,128]
    const float* ln_g   = (const float*)d_in[11];
    const float* ln_b   = (const float*)d_in[12];
    const float* W_out  = (const float*)d_in[13];
    const float* b_out  = (const float*)d_in[14];
    const float* base   = (const float*)d_in[15];
    float* pred = (float*)d_out;

    void *p_h0, *p_h1, *p_ht, *p_inv, *p_cnt, *p_off, *p_cur, *p_elist, *p_bsum;
    cudaGetSymbolAddress(&p_h0, g_h0);
    cudaGetSymbolAddress(&p_h1, g_h1);
    cudaGetSymbolAddress(&p_ht, g_ht);
    cudaGetSymbolAddress(&p_inv, g_inv);
    cudaGetSymbolAddress(&p_cnt, g_cnt);
    cudaGetSymbolAddress(&p_off, g_off);
    cudaGetSymbolAddress(&p_cur, g_cur);
    cudaGetSymbolAddress(&p_elist, g_elist);
    cudaGetSymbolAddress(&p_bsum, g_bsum);
    float*  h0  = (float*)p_h0;
    float*  h1  = (float*)p_h1;
    __half* ht  = (__half*)p_ht;
    float*  inv = (float*)p_inv;
    int* cnt   = (int*)p_cnt;
    int* off   = (int*)p_off;
    int* cur   = (int*)p_cur;
    int* elist = (int*)p_elist;
    int* bsum  = (int*)p_bsum;

    static bool attr_set = false;
    if (!attr_set) {
        cudaFuncSetAttribute(ht_gemm,
                             cudaFuncAttributeMaxDynamicSharedMemorySize,
                             128 * CLDC * sizeof(float));
        attr_set = true;
    }
    const int gemm_smem = 128 * CLDC * sizeof(float);   // 67.6 KB

    // ---- CSR build (once per call; reused by both layers) ----
    cudaMemsetAsync(cnt, 0, (size_t)Nc * Rc * sizeof(int));
    count_kernel<<<Ec / 256, 256>>>(ei, et, cnt);
    scan1_kernel<<<256, 256>>>(cnt, inv, off, bsum);
    scan2_kernel<<<1, 256>>>(bsum);
    scan3_kernel<<<Nc / 256, 256>>>(off, bsum, cur);
    fill_kernel<<<Ec / 256, 256>>>(ei, et, cur, elist);

    // ---- input projections -> h0 ----
    gemm_inproj<<<NAc / BM, 256>>>(xa, 64, 64, W_in_a, b_in_a, h0);
    gemm_inproj<<<NWc / BM, 256>>>(xw, 64, 64, W_in_w, b_in_w, h0 + (size_t)NAc * Hc);

    // ---- layer 0 ----
    ht_gemm<<<dim3(5, Nc / 128), 256, gemm_smem>>>(
        h0, W_root, W_rel, b_conv, ht);
    gather_ln_kernel<false><<<Nc / 8, 256>>>(ht, off, elist, inv,
                                             ln_g, ln_b, h1,
                                             nullptr, nullptr, nullptr);

    // ---- layer 1 (only assignment nodes needed; fused output head) ----
    ht_gemm<<<dim3(5, Nc / 128), 256, gemm_smem>>>(
        h1, W_root + (size_t)Hc * Hc, W_rel + (size_t)Rc * Hc * Hc,
        b_conv + Hc, ht);
    gather_ln_kernel<true><<<NAc / 8, 256>>>(ht, off, elist, inv,
                                             ln_g + Hc, ln_b + Hc, pred,
                                             W_out, b_out, base);
}

// round 6
// speedup vs baseline: 2.2150x; 1.0279x over previous
#include <cuda_runtime.h>
#include <cuda_fp16.h>
#include <cuda_bf16.h>
#include <cstdint>

#define NAc 131072
#define NWc 131072
#define Nc  262144
#define Ec  1048576
#define Hc  128
#define Rc  4
#define HTW 640                      // ht row width: [root | rel0..3]

// ---------------- scratch (static __device__, no runtime alloc) ----------------
__device__ float  g_h0[(size_t)Nc * Hc];            // 128 MB
__device__ float  g_h1[(size_t)Nc * Hc];            // 128 MB
__device__ __half g_ht[(size_t)Nc * HTW];           // 320 MB
__device__ float  g_inv[(size_t)Nc * Rc];           // 4 MB
__device__ int    g_cnt[(size_t)Nc * Rc];           // 4 MB
__device__ int    g_off[Nc + 1];
__device__ int    g_cur[Nc];
__device__ int    g_elist[Ec];
__device__ int    g_bsum[256];

// ---------------- histogram ----------------
__global__ void count_kernel(const int* __restrict__ ei, const int* __restrict__ et,
                             int* __restrict__ cnt) {
    int e = blockIdx.x * blockDim.x + threadIdx.x;
    if (e < Ec) {
        int dst = ei[Ec + e];
        int r = et[e];
        atomicAdd(&cnt[dst * Rc + r], 1);
    }
}

// ---------------- scan stage 1 ----------------
__global__ void __launch_bounds__(256) scan1_kernel(
    const int* __restrict__ cnt, float* __restrict__ inv,
    int* __restrict__ off, int* __restrict__ bsum)
{
    __shared__ int sh[256];
    const int blk = blockIdx.x, tid = threadIdx.x;
    const int base = blk * 1024 + tid * 4;
    int d[4], tot = 0;
#pragma unroll
    for (int j = 0; j < 4; j++) {
        int node = base + j;
        int s = 0;
#pragma unroll
        for (int r = 0; r < 4; r++) {
            int c = cnt[node * 4 + r];
            inv[node * 4 + r] = 1.0f / (float)(c > 0 ? c : 1);
            s += c;
        }
        d[j] = s; tot += s;
    }
    sh[tid] = tot;
    __syncthreads();
    for (int o = 1; o < 256; o <<= 1) {
        int t = (tid >= o) ? sh[tid - o] : 0;
        __syncthreads();
        sh[tid] += t;
        __syncthreads();
    }
    int excl = sh[tid] - tot;
#pragma unroll
    for (int j = 0; j < 4; j++) { off[base + j] = excl; excl += d[j]; }
    if (tid == 255) bsum[blk] = sh[255];
}

// ---------------- scan stage 2 ----------------
__global__ void __launch_bounds__(256) scan2_kernel(int* __restrict__ bsum) {
    __shared__ int sh[256];
    int tid = threadIdx.x;
    int v = bsum[tid];
    sh[tid] = v;
    __syncthreads();
    for (int o = 1; o < 256; o <<= 1) {
        int t = (tid >= o) ? sh[tid - o] : 0;
        __syncthreads();
        sh[tid] += t;
        __syncthreads();
    }
    bsum[tid] = sh[tid] - v;   // exclusive
}

// ---------------- scan stage 3 ----------------
__global__ void scan3_kernel(int* __restrict__ off, const int* __restrict__ bsum,
                             int* __restrict__ cur) {
    int i = blockIdx.x * blockDim.x + threadIdx.x;
    if (i < Nc) {
        int v = off[i] + bsum[i >> 10];
        off[i] = v;
        cur[i] = v;
        if (i == 0) off[Nc] = Ec;
    }
}

// ---------------- CSR fill ----------------
__global__ void fill_kernel(const int* __restrict__ ei, const int* __restrict__ et,
                            int* __restrict__ cur, int* __restrict__ elist) {
    int e = blockIdx.x * blockDim.x + threadIdx.x;
    if (e < Ec) {
        int src = ei[e];
        int dst = ei[Ec + e];
        int r = et[e];
        int pos = atomicAdd(&cur[dst], 1);
        elist[pos] = (src << 2) | r;
    }
}

// ---------------- input projection GEMM (fp32 FFMA, small) ----------------
#define BM 64
#define BN 128
#define BK 16

__global__ void __launch_bounds__(256) gemm_inproj(
    const float* __restrict__ A1, int lda1, int K1, const float* __restrict__ B1,
    const float* __restrict__ bias, float* __restrict__ out)
{
    __shared__ float As[BK][BM + 4];
    __shared__ float Bs[BK][BN];

    const int tid  = threadIdx.x;
    const int row0 = blockIdx.x * BM;
    const int tr = tid >> 5;
    const int tc = tid & 31;

    float acc[8][4];
#pragma unroll
    for (int i = 0; i < 8; i++)
#pragma unroll
        for (int j = 0; j < 4; j++) acc[i][j] = 0.0f;

    const int ar = tid >> 2;
    const int ac = (tid & 3) << 2;
    const int br = tid >> 5;
    const int bc = (tid & 31) << 2;

    for (int k0 = 0; k0 < K1; k0 += BK) {
        float4 av = *(const float4*)&A1[(size_t)(row0 + ar) * lda1 + k0 + ac];
        As[ac + 0][ar] = av.x;
        As[ac + 1][ar] = av.y;
        As[ac + 2][ar] = av.z;
        As[ac + 3][ar] = av.w;
        *(float4*)&Bs[br][bc]     = *(const float4*)&B1[(size_t)(k0 + br) * BN + bc];
        *(float4*)&Bs[br + 8][bc] = *(const float4*)&B1[(size_t)(k0 + br + 8) * BN + bc];
        __syncthreads();
#pragma unroll
        for (int k = 0; k < BK; k++) {
            float4 b = *(const float4*)&Bs[k][tc << 2];
            float4 a0 = *(const float4*)&As[k][tr << 3];
            float4 a1 = *(const float4*)&As[k][(tr << 3) + 4];
            float a[8] = {a0.x, a0.y, a0.z, a0.w, a1.x, a1.y, a1.z, a1.w};
#pragma unroll
            for (int i = 0; i < 8; i++) {
                acc[i][0] += a[i] * b.x;
                acc[i][1] += a[i] * b.y;
                acc[i][2] += a[i] * b.z;
                acc[i][3] += a[i] * b.w;
            }
        }
        __syncthreads();
    }

    float4 bv = *(const float4*)&bias[tc << 2];
#pragma unroll
    for (int i = 0; i < 8; i++) {
        float4 o;
        o.x = fmaxf(acc[i][0] + bv.x, 0.0f);
        o.y = fmaxf(acc[i][1] + bv.y, 0.0f);
        o.z = fmaxf(acc[i][2] + bv.z, 0.0f);
        o.w = fmaxf(acc[i][3] + bv.w, 0.0f);
        *(float4*)&out[(size_t)(row0 + (tr << 3) + i) * Hc + (tc << 2)] = o;
    }
}

// ---------------- ht GEMM: ht[:, cb*128:(cb+1)*128] = h @ Bsel (+bias if cb==0) ----
#define CBUF   5120
#define CLDC   132

__device__ __forceinline__ uint32_t f2tf(float f) {
    uint32_t u;
    asm("cvt.rna.tf32.f32 %0, %1;" : "=r"(u) : "f"(f));
    return u;
}

__device__ __forceinline__ void mma_tf32(float c[4], const uint32_t a[4], const uint32_t b[2]) {
    asm volatile(
        "mma.sync.aligned.m16n8k8.row.col.f32.tf32.tf32.f32 "
        "{%0,%1,%2,%3}, {%4,%5,%6,%7}, {%8,%9}, {%0,%1,%2,%3};"
        : "+f"(c[0]), "+f"(c[1]), "+f"(c[2]), "+f"(c[3])
        : "r"(a[0]), "r"(a[1]), "r"(a[2]), "r"(a[3]), "r"(b[0]), "r"(b[1]));
}

__device__ __forceinline__ void ldsm4(uint32_t& r0, uint32_t& r1, uint32_t& r2, uint32_t& r3,
                                      uint32_t addr) {
    asm volatile("ldmatrix.sync.aligned.m8n8.x4.shared.b16 {%0,%1,%2,%3}, [%4];"
                 : "=r"(r0), "=r"(r1), "=r"(r2), "=r"(r3) : "r"(addr));
}

extern __shared__ float dyn_smem[];

__global__ void __launch_bounds__(256) ht_gemm(
    const float* __restrict__ A,        // h [N,128]
    const float* __restrict__ W_root,   // layer's [128,128]
    const float* __restrict__ W_rel,    // layer's [4,128,128]
    const float* __restrict__ bias,     // layer's [128]
    __half* __restrict__ ht,
    int rootRowLimit)                   // root cols only needed for rows < limit
{
    const int cb = blockIdx.x;                 // column block 0..4
    const size_t row0 = (size_t)blockIdx.y * 128;
    if (cb == 0 && row0 >= (size_t)rootRowLimit) return;
    const float* B = (cb == 0) ? W_root : (W_rel + (size_t)(cb - 1) * Hc * Hc);

    const int tid  = threadIdx.x;
    const int lane = tid & 31;
    const int wid  = tid >> 5;
    const int m0 = (wid >> 1) * 32;
    const int n0 = (wid & 1) * 64;

    uint32_t smem_u;
    asm("{.reg .u64 t; cvta.to.shared.u64 t, %1; cvt.u32.u64 %0, t;}"
        : "=r"(smem_u) : "l"(dyn_smem));

    const uint32_t aLane = ((lane & 7) + ((lane >> 3) & 1) * 8) * 80 + ((lane >> 4) & 1) * 16;
    const uint32_t bLane = ((lane & 7) + ((lane >> 4) & 1) * 8) * 80 + ((lane >> 3) & 1) * 16;

    const int s_ar = tid >> 2;
    const int s_ac = (tid & 3) << 2;
    const int s_bn = tid >> 1;
    const int s_bk = (tid & 1) << 3;

    float acc[2][8][4];
#pragma unroll
    for (int mi = 0; mi < 2; mi++)
#pragma unroll
        for (int ni = 0; ni < 8; ni++)
#pragma unroll
            for (int j = 0; j < 4; j++) acc[mi][ni][j] = 0.0f;

    auto stage = [&](int s, int buf) {
        int k0 = s * 16;
        float* As = dyn_smem + buf * CBUF;
        float* Bs = As + 2560;
#pragma unroll
        for (int i = 0; i < 2; i++) {
            int ar = s_ar + i * 64;
            float4 av = *(const float4*)&A[(row0 + ar) * (size_t)Hc + k0 + s_ac];
            uint4 u;
            u.x = f2tf(av.x); u.y = f2tf(av.y); u.z = f2tf(av.z); u.w = f2tf(av.w);
            *(uint4*)((char*)As + ar * 80 + s_ac * 4) = u;
        }
        uint32_t bv[8];
#pragma unroll
        for (int j = 0; j < 8; j++) bv[j] = f2tf(B[(size_t)(k0 + s_bk + j) * Hc + s_bn]);
        *(uint4*)((char*)Bs + s_bn * 80 + s_bk * 4)      = make_uint4(bv[0], bv[1], bv[2], bv[3]);
        *(uint4*)((char*)Bs + s_bn * 80 + s_bk * 4 + 16) = make_uint4(bv[4], bv[5], bv[6], bv[7]);
    };

    stage(0, 0);
    __syncthreads();

    for (int s = 0; s < 8; s++) {
        int buf = s & 1;
        if (s + 1 < 8) stage(s + 1, buf ^ 1);

        uint32_t Abase = smem_u + buf * (CBUF * 4);
        uint32_t Bbase = Abase + 2560 * 4;
#pragma unroll
        for (int kk = 0; kk < 16; kk += 8) {
            uint32_t a[2][4];
#pragma unroll
            for (int mi = 0; mi < 2; mi++)
                ldsm4(a[mi][0], a[mi][1], a[mi][2], a[mi][3],
                      Abase + (m0 + mi * 16) * 80 + kk * 4 + aLane);
            uint32_t b[8][2];
#pragma unroll
            for (int nip = 0; nip < 4; nip++)
                ldsm4(b[2 * nip][0], b[2 * nip][1], b[2 * nip + 1][0], b[2 * nip + 1][1],
                      Bbase + (n0 + nip * 16) * 80 + kk * 4 + bLane);
#pragma unroll
            for (int mi = 0; mi < 2; mi++)
#pragma unroll
                for (int ni = 0; ni < 8; ni++)
                    mma_tf32(acc[mi][ni], a[mi], b[ni]);
        }
        __syncthreads();
    }

    // epilogue: via smem, then fp16 coalesced stores
    float* Cs = dyn_smem;
    const int t = lane & 3;
    const int g = lane >> 2;
#pragma unroll
    for (int mi = 0; mi < 2; mi++) {
        int r = m0 + mi * 16 + g;
#pragma unroll
        for (int ni = 0; ni < 8; ni++) {
            int cc = n0 + ni * 8 + 2 * t;
            Cs[r * CLDC + cc]           = acc[mi][ni][0];
            Cs[r * CLDC + cc + 1]       = acc[mi][ni][1];
            Cs[(r + 8) * CLDC + cc]     = acc[mi][ni][2];
            Cs[(r + 8) * CLDC + cc + 1] = acc[mi][ni][3];
        }
    }
    __syncthreads();

    float4 bv = make_float4(0.f, 0.f, 0.f, 0.f);
    if (cb == 0) bv = *(const float4*)&bias[lane << 2];
#pragma unroll
    for (int rr = 0; rr < 16; rr++) {
        int r = wid * 16 + rr;
        float4 x = *(float4*)&Cs[r * CLDC + (lane << 2)];
        x.x += bv.x; x.y += bv.y; x.z += bv.z; x.w += bv.w;
        __half2 p0 = __floats2half2_rn(x.x, x.y);
        __half2 p1 = __floats2half2_rn(x.z, x.w);
        uint2 u = make_uint2(*(uint32_t*)&p0, *(uint32_t*)&p1);
        *(uint2*)&ht[(row0 + r) * HTW + cb * Hc + (lane << 2)] = u;
    }
}

// ---------------- gather + LN + ReLU (+ optional fused output head) ----------------
// one warp per dst node; half-warp per edge, 4 edges in flight per loop trip.
// lane (0..31): half = lane>>4, sub = lane&15. Lane accumulates cols sub*8..sub*8+7.
template<bool HEAD>
__global__ void __launch_bounds__(256) gather_ln_kernel(
    const __half* __restrict__ ht, const int* __restrict__ off,
    const int* __restrict__ elist, const float* __restrict__ inv,
    const float* __restrict__ lng, const float* __restrict__ lnb,
    float* __restrict__ out,
    const float* __restrict__ Wout, const float* __restrict__ bout,
    const float* __restrict__ basep)
{
    const int warp = threadIdx.x >> 5;
    const int lane = threadIdx.x & 31;
    const int half = lane >> 4;
    const int sub  = lane & 15;
    const int d = blockIdx.x * 8 + warp;

    float a[8];
#pragma unroll
    for (int j = 0; j < 8; j++) a[j] = 0.0f;

    // root slice: lanes 0-15 load 16B each (full 256B row)
    if (half == 0) {
        uint4 v = *(const uint4*)&ht[(size_t)d * HTW + sub * 8];
        const __half2* h2 = (const __half2*)&v;
#pragma unroll
        for (int j = 0; j < 4; j++) {
            float2 f = __half22float2(h2[j]);
            a[2 * j]     = f.x;
            a[2 * j + 1] = f.y;
        }
    }

    const float4 iv = *(const float4*)&inv[d * 4];
    const int e0 = __ldg(&off[d]);
    const int e1 = __ldg(&off[d + 1]);

    for (int e = e0; e < e1; e += 4) {
#pragma unroll
        for (int q = 0; q < 2; q++) {
            int i = e + half + q * 2;
            if (i < e1) {
                int p = __ldg(&elist[i]);
                int src = p >> 2;
                int r = p & 3;
                float s = (r & 1) ? ((r & 2) ? iv.w : iv.y) : ((r & 2) ? iv.z : iv.x);
                uint4 v = *(const uint4*)&ht[(size_t)src * HTW + (1 + r) * Hc + sub * 8];
                const __half2* h2 = (const __half2*)&v;
#pragma unroll
                for (int j = 0; j < 4; j++) {
                    float2 f = __half22float2(h2[j]);
                    a[2 * j]     += s * f.x;
                    a[2 * j + 1] += s * f.y;
                }
            }
        }
    }

    // combine the two half-warps (both halves end with the full sum)
#pragma unroll
    for (int j = 0; j < 8; j++) a[j] += __shfl_xor_sync(0xffffffffu, a[j], 16);

    // LayerNorm stats over 128 cols (reduce over 16 lanes within each half)
    float sum = 0.f, sq = 0.f;
#pragma unroll
    for (int j = 0; j < 8; j++) { sum += a[j]; sq += a[j] * a[j]; }
#pragma unroll
    for (int o = 8; o; o >>= 1) {
        sum += __shfl_xor_sync(0xffffffffu, sum, o);
        sq  += __shfl_xor_sync(0xffffffffu, sq, o);
    }
    const float inv128 = 1.0f / 128.0f;
    float mu  = sum * inv128;
    float var = sq * inv128 - mu * mu;
    float rs  = rsqrtf(var + 1e-5f);

    float o8[8];
    float4 gv0  = *(const float4*)&lng[sub * 8];
    float4 gv1  = *(const float4*)&lng[sub * 8 + 4];
    float4 lb0  = *(const float4*)&lnb[sub * 8];
    float4 lb1  = *(const float4*)&lnb[sub * 8 + 4];
    const float gg[8] = {gv0.x, gv0.y, gv0.z, gv0.w, gv1.x, gv1.y, gv1.z, gv1.w};
    const float bb[8] = {lb0.x, lb0.y, lb0.z, lb0.w, lb1.x, lb1.y, lb1.z, lb1.w};
#pragma unroll
    for (int j = 0; j < 8; j++)
        o8[j] = fmaxf((a[j] - mu) * rs * gg[j] + bb[j], 0.0f);

    if (HEAD) {
        float4 w0 = *(const float4*)&Wout[sub * 8];
        float4 w1 = *(const float4*)&Wout[sub * 8 + 4];
        const float ww[8] = {w0.x, w0.y, w0.z, w0.w, w1.x, w1.y, w1.z, w1.w};
        float s = 0.f;
#pragma unroll
        for (int j = 0; j < 8; j++) s += o8[j] * ww[j];
#pragma unroll
        for (int o = 8; o; o >>= 1) s += __shfl_xor_sync(0xffffffffu, s, o);
        if (lane == 0) out[d] = basep[0] + s + bout[0];
    } else {
        // lanes 0-15 store cols sub*8..+3; lanes 16-31 store cols sub*8+4..+7
        float4 st = half ? make_float4(o8[4], o8[5], o8[6], o8[7])
                         : make_float4(o8[0], o8[1], o8[2], o8[3]);
        *(float4*)&out[(size_t)d * Hc + sub * 8 + half * 4] = st;
    }
}

// ---------------- launch ----------------
extern "C" void kernel_launch(void* const* d_in, const int* in_sizes, int n_in,
                              void* d_out, int out_size)
{
    const float* xa     = (const float*)d_in[0];
    const float* xw     = (const float*)d_in[1];
    const int*   ei     = (const int*)  d_in[2];
    const int*   et     = (const int*)  d_in[3];
    const float* W_in_a = (const float*)d_in[4];
    const float* b_in_a = (const float*)d_in[5];
    const float* W_in_w = (const float*)d_in[6];
    const float* b_in_w = (const float*)d_in[7];
    const float* W_rel  = (const float*)d_in[8];   // [2,4,128,128]
    const float* W_root = (const float*)d_in[9];   // [2,128,128]
    const float* b_conv = (const float*)d_in[10];  // [2,128]
    const float* ln_g   = (const float*)d_in[11];
    const float* ln_b   = (const float*)d_in[12];
    const float* W_out  = (const float*)d_in[13];
    const float* b_out  = (const float*)d_in[14];
    const float* base   = (const float*)d_in[15];
    float* pred = (float*)d_out;

    void *p_h0, *p_h1, *p_ht, *p_inv, *p_cnt, *p_off, *p_cur, *p_elist, *p_bsum;
    cudaGetSymbolAddress(&p_h0, g_h0);
    cudaGetSymbolAddress(&p_h1, g_h1);
    cudaGetSymbolAddress(&p_ht, g_ht);
    cudaGetSymbolAddress(&p_inv, g_inv);
    cudaGetSymbolAddress(&p_cnt, g_cnt);
    cudaGetSymbolAddress(&p_off, g_off);
    cudaGetSymbolAddress(&p_cur, g_cur);
    cudaGetSymbolAddress(&p_elist, g_elist);
    cudaGetSymbolAddress(&p_bsum, g_bsum);
    float*  h0  = (float*)p_h0;
    float*  h1  = (float*)p_h1;
    __half* ht  = (__half*)p_ht;
    float*  inv = (float*)p_inv;
    int* cnt   = (int*)p_cnt;
    int* off   = (int*)p_off;
    int* cur   = (int*)p_cur;
    int* elist = (int*)p_elist;
    int* bsum  = (int*)p_bsum;

    static bool attr_set = false;
    if (!attr_set) {
        cudaFuncSetAttribute(ht_gemm,
                             cudaFuncAttributeMaxDynamicSharedMemorySize,
                             128 * CLDC * sizeof(float));
        attr_set = true;
    }
    const int gemm_smem = 128 * CLDC * sizeof(float);   // 67.6 KB

    // ---- CSR build (once per call; reused by both layers) ----
    cudaMemsetAsync(cnt, 0, (size_t)Nc * Rc * sizeof(int));
    count_kernel<<<Ec / 256, 256>>>(ei, et, cnt);
    scan1_kernel<<<256, 256>>>(cnt, inv, off, bsum);
    scan2_kernel<<<1, 256>>>(bsum);
    scan3_kernel<<<Nc / 256, 256>>>(off, bsum, cur);
    fill_kernel<<<Ec / 256, 256>>>(ei, et, cur, elist);

    // ---- input projections -> h0 ----
    gemm_inproj<<<NAc / BM, 256>>>(xa, 64, 64, W_in_a, b_in_a, h0);
    gemm_inproj<<<NWc / BM, 256>>>(xw, 64, 64, W_in_w, b_in_w, h0 + (size_t)NAc * Hc);

    // ---- layer 0 ----
    ht_gemm<<<dim3(5, Nc / 128), 256, gemm_smem>>>(
        h0, W_root, W_rel, b_conv, ht, Nc);
    gather_ln_kernel<false><<<Nc / 8, 256>>>(ht, off, elist, inv,
                                             ln_g, ln_b, h1,
                                             nullptr, nullptr, nullptr);

    // ---- layer 1 (root cols only for assignment nodes; fused output head) ----
    ht_gemm<<<dim3(5, Nc / 128), 256, gemm_smem>>>(
        h1, W_root + (size_t)Hc * Hc, W_rel + (size_t)Rc * Hc * Hc,
        b_conv + Hc, ht, NAc);
    gather_ln_kernel<true><<<NAc / 8, 256>>>(ht, off, elist, inv,
                                             ln_g + Hc, ln_b + Hc, pred,
                                             W_out, b_out, base);
}

// round 8
// speedup vs baseline: 3.3378x; 1.5069x over previous
#include <cuda_runtime.h>
#include <cuda_fp16.h>
#include <cuda_bf16.h>
#include <cstdint>

#define NAc 131072
#define NWc 131072
#define Nc  262144
#define Ec  1048576
#define Hc  128
#define Rc  4
#define HTW 640                      // ht row width: [root | rel0..3]

// ---------------- scratch (static __device__, no runtime alloc) ----------------
__device__ __half g_h0[(size_t)Nc * Hc];            // 64 MB
__device__ __half g_h1[(size_t)Nc * Hc];            // 64 MB
__device__ __half g_ht[(size_t)Nc * HTW];           // 320 MB
__device__ __half g_wt[180224];                     // fp16 transposed weights
__device__ float  g_inv[(size_t)Nc * Rc];           // 4 MB
__device__ int    g_cnt[(size_t)Nc * Rc];           // 4 MB
__device__ int    g_off[Nc + 1];
__device__ int    g_cur[Nc];
__device__ int    g_elist[Ec];
__device__ int    g_bsum[256];

// g_wt layout (halves):
//   [0      : 8192)   W_in_a^T  [n=128][k=64]
//   [8192   : 16384)  W_in_w^T  [n=128][k=64]
//   [16384 + (l*5+cb)*16384 ...)  layer l, col-block cb: W^T [n=128][k=128]
#define WT_CONV_OFF 16384

// ---------------- weight prep: transpose + fp16 convert ----------------
__global__ void prep_wt(const float* __restrict__ Wa, const float* __restrict__ Ww,
                        const float* __restrict__ Wroot, const float* __restrict__ Wrel,
                        __half* __restrict__ wt)
{
    int i = blockIdx.x * 256 + threadIdx.x;
    if (i >= 180224) return;
    if (i < 16384) {
        int which = i >> 13;
        int j = i & 8191;
        int n = j >> 6, k = j & 63;
        const float* W = which ? Ww : Wa;
        wt[i] = __float2half(W[k * 128 + n]);
    } else {
        int j = i - 16384;
        int mat = j >> 14;                       // 0..9
        int jj = j & 16383;
        int n = jj >> 7, k = jj & 127;
        int l = mat / 5, cb = mat % 5;
        const float* W = (cb == 0) ? (Wroot + (size_t)l * 16384)
                                   : (Wrel + ((size_t)l * 4 + (cb - 1)) * 16384);
        wt[i] = __float2half(W[k * 128 + n]);
    }
}

// ---------------- histogram ----------------
__global__ void count_kernel(const int* __restrict__ ei, const int* __restrict__ et,
                             int* __restrict__ cnt) {
    int e = blockIdx.x * blockDim.x + threadIdx.x;
    if (e < Ec) {
        int dst = ei[Ec + e];
        int r = et[e];
        atomicAdd(&cnt[dst * Rc + r], 1);
    }
}

// ---------------- scan stage 1 ----------------
__global__ void __launch_bounds__(256) scan1_kernel(
    const int* __restrict__ cnt, float* __restrict__ inv,
    int* __restrict__ off, int* __restrict__ bsum)
{
    __shared__ int sh[256];
    const int blk = blockIdx.x, tid = threadIdx.x;
    const int base = blk * 1024 + tid * 4;
    int d[4], tot = 0;
#pragma unroll
    for (int j = 0; j < 4; j++) {
        int node = base + j;
        int s = 0;
#pragma unroll
        for (int r = 0; r < 4; r++) {
            int c = cnt[node * 4 + r];
            inv[node * 4 + r] = 1.0f / (float)(c > 0 ? c : 1);
            s += c;
        }
        d[j] = s; tot += s;
    }
    sh[tid] = tot;
    __syncthreads();
    for (int o = 1; o < 256; o <<= 1) {
        int t = (tid >= o) ? sh[tid - o] : 0;
        __syncthreads();
        sh[tid] += t;
        __syncthreads();
    }
    int excl = sh[tid] - tot;
#pragma unroll
    for (int j = 0; j < 4; j++) { off[base + j] = excl; excl += d[j]; }
    if (tid == 255) bsum[blk] = sh[255];
}

// ---------------- scan stage 2 ----------------
__global__ void __launch_bounds__(256) scan2_kernel(int* __restrict__ bsum) {
    __shared__ int sh[256];
    int tid = threadIdx.x;
    int v = bsum[tid];
    sh[tid] = v;
    __syncthreads();
    for (int o = 1; o < 256; o <<= 1) {
        int t = (tid >= o) ? sh[tid - o] : 0;
        __syncthreads();
        sh[tid] += t;
        __syncthreads();
    }
    bsum[tid] = sh[tid] - v;   // exclusive
}

// ---------------- scan stage 3 ----------------
__global__ void scan3_kernel(int* __restrict__ off, const int* __restrict__ bsum,
                             int* __restrict__ cur) {
    int i = blockIdx.x * blockDim.x + threadIdx.x;
    if (i < Nc) {
        int v = off[i] + bsum[i >> 10];
        off[i] = v;
        cur[i] = v;
        if (i == 0) off[Nc] = Ec;
    }
}

// ---------------- CSR fill ----------------
__global__ void fill_kernel(const int* __restrict__ ei, const int* __restrict__ et,
                            int* __restrict__ cur, int* __restrict__ elist) {
    int e = blockIdx.x * blockDim.x + threadIdx.x;
    if (e < Ec) {
        int src = ei[e];
        int dst = ei[Ec + e];
        int r = et[e];
        int pos = atomicAdd(&cur[dst], 1);
        elist[pos] = (src << 2) | r;
    }
}

// ================== fp16 MMA building blocks ==================
#define CLDC   132
#define STG_BUF 20480               // bytes per stage buffer (A 10240 + B 10240)

__device__ __forceinline__ void mma_f16(float c[4], const uint32_t a[4], const uint32_t b[2]) {
    asm volatile(
        "mma.sync.aligned.m16n8k16.row.col.f32.f16.f16.f32 "
        "{%0,%1,%2,%3}, {%4,%5,%6,%7}, {%8,%9}, {%0,%1,%2,%3};"
        : "+f"(c[0]), "+f"(c[1]), "+f"(c[2]), "+f"(c[3])
        : "r"(a[0]), "r"(a[1]), "r"(a[2]), "r"(a[3]), "r"(b[0]), "r"(b[1]));
}

__device__ __forceinline__ void ldsm4(uint32_t& r0, uint32_t& r1, uint32_t& r2, uint32_t& r3,
                                      uint32_t addr) {
    asm volatile("ldmatrix.sync.aligned.m8n8.x4.shared.b16 {%0,%1,%2,%3}, [%4];"
                 : "=r"(r0), "=r"(r1), "=r"(r2), "=r"(r3) : "r"(addr));
}

extern __shared__ float dyn_smem[];

// ---------------- ht GEMM (fp16 in, fp16 out): ht[:, cb*128:+128] = h @ WtT[cb] ----
__global__ void __launch_bounds__(256) ht_gemm_f16(
    const __half* __restrict__ A,        // h [N,128] fp16
    const __half* __restrict__ wt,       // g_wt
    int layer,
    const float* __restrict__ bias,      // layer's [128] (cb==0 only)
    __half* __restrict__ ht,
    int rootRowLimit)
{
    const int cb = blockIdx.x;
    const size_t row0 = (size_t)blockIdx.y * 128;
    if (cb == 0 && row0 >= (size_t)rootRowLimit) return;
    const __half* Bt = wt + WT_CONV_OFF + (size_t)(layer * 5 + cb) * 16384;  // [n=128][k=128]

    const int tid  = threadIdx.x;
    const int lane = tid & 31;
    const int wid  = tid >> 5;
    const int m0 = (wid >> 1) * 32;
    const int n0 = (wid & 1) * 64;
    const int half_ = lane >> 4;
    const int sub   = lane & 15;

    uint32_t smem_u;
    asm("{.reg .u64 t; cvta.to.shared.u64 t, %1; cvt.u32.u64 %0, t;}"
        : "=r"(smem_u) : "l"(dyn_smem));

    const uint32_t aLane = ((lane & 7) + ((lane >> 3) & 1) * 8) * 80 + ((lane >> 4) & 1) * 16;
    const uint32_t bLane = ((lane & 7) + ((lane >> 4) & 1) * 8) * 80 + ((lane >> 3) & 1) * 16;

    const int s_ar = tid >> 2;            // 0..63
    const int s_ac = (tid & 3) << 3;      // half-index 0,8,16,24

    float acc[2][8][4];
#pragma unroll
    for (int mi = 0; mi < 2; mi++)
#pragma unroll
        for (int ni = 0; ni < 8; ni++)
#pragma unroll
            for (int j = 0; j < 4; j++) acc[mi][ni][j] = 0.0f;

    auto stage = [&](int s, int buf) {
        int k0 = s * 32;
        char* base = (char*)dyn_smem + buf * STG_BUF;
#pragma unroll
        for (int i = 0; i < 2; i++) {
            int ar = s_ar + i * 64;
            uint4 av = *(const uint4*)&A[(row0 + ar) * (size_t)Hc + k0 + s_ac];
            *(uint4*)(base + ar * 80 + s_ac * 2) = av;
            uint4 bv = *(const uint4*)&Bt[(size_t)ar * 128 + k0 + s_ac];
            *(uint4*)(base + 10240 + ar * 80 + s_ac * 2) = bv;
        }
    };

    stage(0, 0);
    __syncthreads();

    for (int s = 0; s < 4; s++) {
        int buf = s & 1;
        if (s + 1 < 4) stage(s + 1, buf ^ 1);

        uint32_t Abase = smem_u + buf * STG_BUF;
        uint32_t Bbase = Abase + 10240;
#pragma unroll
        for (int kk = 0; kk < 32; kk += 16) {
            uint32_t a[2][4];
#pragma unroll
            for (int mi = 0; mi < 2; mi++)
                ldsm4(a[mi][0], a[mi][1], a[mi][2], a[mi][3],
                      Abase + (m0 + mi * 16) * 80 + kk * 2 + aLane);
            uint32_t b[8][2];
#pragma unroll
            for (int nip = 0; nip < 4; nip++)
                ldsm4(b[2 * nip][0], b[2 * nip][1], b[2 * nip + 1][0], b[2 * nip + 1][1],
                      Bbase + (n0 + nip * 16) * 80 + kk * 2 + bLane);
#pragma unroll
            for (int mi = 0; mi < 2; mi++)
#pragma unroll
                for (int ni = 0; ni < 8; ni++)
                    mma_f16(acc[mi][ni], a[mi], b[ni]);
        }
        __syncthreads();
    }

    // epilogue: fp32 dump to smem, then fp16 stores
    float* Cs = dyn_smem;
    const int t = lane & 3;
    const int g = lane >> 2;
#pragma unroll
    for (int mi = 0; mi < 2; mi++) {
        int r = m0 + mi * 16 + g;
#pragma unroll
        for (int ni = 0; ni < 8; ni++) {
            int cc = n0 + ni * 8 + 2 * t;
            Cs[r * CLDC + cc]           = acc[mi][ni][0];
            Cs[r * CLDC + cc + 1]       = acc[mi][ni][1];
            Cs[(r + 8) * CLDC + cc]     = acc[mi][ni][2];
            Cs[(r + 8) * CLDC + cc + 1] = acc[mi][ni][3];
        }
    }
    __syncthreads();

    float4 bv0 = make_float4(0.f, 0.f, 0.f, 0.f);
    float4 bv1 = bv0;
    if (cb == 0) {
        bv0 = *(const float4*)&bias[sub * 8];
        bv1 = *(const float4*)&bias[sub * 8 + 4];
    }
#pragma unroll
    for (int rr = 0; rr < 8; rr++) {
        int r = wid * 16 + rr * 2 + half_;
        float4 x0 = *(float4*)&Cs[r * CLDC + sub * 8];
        float4 x1 = *(float4*)&Cs[r * CLDC + sub * 8 + 4];
        x0.x += bv0.x; x0.y += bv0.y; x0.z += bv0.z; x0.w += bv0.w;
        x1.x += bv1.x; x1.y += bv1.y; x1.z += bv1.z; x1.w += bv1.w;
        __half2 p0 = __floats2half2_rn(x0.x, x0.y);
        __half2 p1 = __floats2half2_rn(x0.z, x0.w);
        __half2 p2 = __floats2half2_rn(x1.x, x1.y);
        __half2 p3 = __floats2half2_rn(x1.z, x1.w);
        uint4 u = make_uint4(*(uint32_t*)&p0, *(uint32_t*)&p1,
                             *(uint32_t*)&p2, *(uint32_t*)&p3);
        *(uint4*)&ht[(row0 + r) * HTW + cb * Hc + sub * 8] = u;
    }
}

// ---------------- input projection (fp32 x -> fp16 MMA -> relu -> fp16 h) ----------
__global__ void __launch_bounds__(256) inproj_f16(
    const float* __restrict__ X,         // [Nrows, 64] fp32
    const __half* __restrict__ Bt,       // [n=128][k=64] fp16
    const float* __restrict__ bias,      // [128]
    __half* __restrict__ out)            // [Nrows, 128] fp16
{
    const size_t row0 = (size_t)blockIdx.x * 128;

    const int tid  = threadIdx.x;
    const int lane = tid & 31;
    const int wid  = tid >> 5;
    const int m0 = (wid >> 1) * 32;
    const int n0 = (wid & 1) * 64;
    const int half_ = lane >> 4;
    const int sub   = lane & 15;

    uint32_t smem_u;
    asm("{.reg .u64 t; cvta.to.shared.u64 t, %1; cvt.u32.u64 %0, t;}"
        : "=r"(smem_u) : "l"(dyn_smem));

    const uint32_t aLane = ((lane & 7) + ((lane >> 3) & 1) * 8) * 80 + ((lane >> 4) & 1) * 16;
    const uint32_t bLane = ((lane & 7) + ((lane >> 4) & 1) * 8) * 80 + ((lane >> 3) & 1) * 16;

    const int s_ar = tid >> 2;
    const int s_ac = (tid & 3) << 3;

    float acc[2][8][4];
#pragma unroll
    for (int mi = 0; mi < 2; mi++)
#pragma unroll
        for (int ni = 0; ni < 8; ni++)
#pragma unroll
            for (int j = 0; j < 4; j++) acc[mi][ni][j] = 0.0f;

    auto stage = [&](int s, int buf) {
        int k0 = s * 32;
        char* base = (char*)dyn_smem + buf * STG_BUF;
#pragma unroll
        for (int i = 0; i < 2; i++) {
            int ar = s_ar + i * 64;
            float4 f0 = *(const float4*)&X[(row0 + ar) * 64 + k0 + s_ac];
            float4 f1 = *(const float4*)&X[(row0 + ar) * 64 + k0 + s_ac + 4];
            __half2 p0 = __floats2half2_rn(f0.x, f0.y);
            __half2 p1 = __floats2half2_rn(f0.z, f0.w);
            __half2 p2 = __floats2half2_rn(f1.x, f1.y);
            __half2 p3 = __floats2half2_rn(f1.z, f1.w);
            uint4 u = make_uint4(*(uint32_t*)&p0, *(uint32_t*)&p1,
                                 *(uint32_t*)&p2, *(uint32_t*)&p3);
            *(uint4*)(base + ar * 80 + s_ac * 2) = u;
            uint4 bvv = *(const uint4*)&Bt[(size_t)ar * 64 + k0 + s_ac];
            *(uint4*)(base + 10240 + ar * 80 + s_ac * 2) = bvv;
        }
    };

    stage(0, 0);
    __syncthreads();

    for (int s = 0; s < 2; s++) {
        int buf = s & 1;
        if (s + 1 < 2) stage(s + 1, buf ^ 1);

        uint32_t Abase = smem_u + buf * STG_BUF;
        uint32_t Bbase = Abase + 10240;
#pragma unroll
        for (int kk = 0; kk < 32; kk += 16) {
            uint32_t a[2][4];
#pragma unroll
            for (int mi = 0; mi < 2; mi++)
                ldsm4(a[mi][0], a[mi][1], a[mi][2], a[mi][3],
                      Abase + (m0 + mi * 16) * 80 + kk * 2 + aLane);
            uint32_t b[8][2];
#pragma unroll
            for (int nip = 0; nip < 4; nip++)
                ldsm4(b[2 * nip][0], b[2 * nip][1], b[2 * nip + 1][0], b[2 * nip + 1][1],
                      Bbase + (n0 + nip * 16) * 80 + kk * 2 + bLane);
#pragma unroll
            for (int mi = 0; mi < 2; mi++)
#pragma unroll
                for (int ni = 0; ni < 8; ni++)
                    mma_f16(acc[mi][ni], a[mi], b[ni]);
        }
        __syncthreads();
    }

    float* Cs = dyn_smem;
    const int t = lane & 3;
    const int g = lane >> 2;
#pragma unroll
    for (int mi = 0; mi < 2; mi++) {
        int r = m0 + mi * 16 + g;
#pragma unroll
        for (int ni = 0; ni < 8; ni++) {
            int cc = n0 + ni * 8 + 2 * t;
            Cs[r * CLDC + cc]           = acc[mi][ni][0];
            Cs[r * CLDC + cc + 1]       = acc[mi][ni][1];
            Cs[(r + 8) * CLDC + cc]     = acc[mi][ni][2];
            Cs[(r + 8) * CLDC + cc + 1] = acc[mi][ni][3];
        }
    }
    __syncthreads();

    float4 bv0 = *(const float4*)&bias[sub * 8];
    float4 bv1 = *(const float4*)&bias[sub * 8 + 4];
#pragma unroll
    for (int rr = 0; rr < 8; rr++) {
        int r = wid * 16 + rr * 2 + half_;
        float4 x0 = *(float4*)&Cs[r * CLDC + sub * 8];
        float4 x1 = *(float4*)&Cs[r * CLDC + sub * 8 + 4];
        x0.x = fmaxf(x0.x + bv0.x, 0.f); x0.y = fmaxf(x0.y + bv0.y, 0.f);
        x0.z = fmaxf(x0.z + bv0.z, 0.f); x0.w = fmaxf(x0.w + bv0.w, 0.f);
        x1.x = fmaxf(x1.x + bv1.x, 0.f); x1.y = fmaxf(x1.y + bv1.y, 0.f);
        x1.z = fmaxf(x1.z + bv1.z, 0.f); x1.w = fmaxf(x1.w + bv1.w, 0.f);
        __half2 p0 = __floats2half2_rn(x0.x, x0.y);
        __half2 p1 = __floats2half2_rn(x0.z, x0.w);
        __half2 p2 = __floats2half2_rn(x1.x, x1.y);
        __half2 p3 = __floats2half2_rn(x1.z, x1.w);
        uint4 u = make_uint4(*(uint32_t*)&p0, *(uint32_t*)&p1,
                             *(uint32_t*)&p2, *(uint32_t*)&p3);
        *(uint4*)&out[(row0 + r) * Hc + sub * 8] = u;
    }
}

// ---------------- gather + LN + ReLU (+ optional fused output head) ----------------
template<bool HEAD>
__global__ void __launch_bounds__(256) gather_ln_kernel(
    const __half* __restrict__ ht, const int* __restrict__ off,
    const int* __restrict__ elist, const float* __restrict__ inv,
    const float* __restrict__ lng, const float* __restrict__ lnb,
    void* __restrict__ out_v,
    const float* __restrict__ Wout, const float* __restrict__ bout,
    const float* __restrict__ basep)
{
    const int warp = threadIdx.x >> 5;
    const int lane = threadIdx.x & 31;
    const int half = lane >> 4;
    const int sub  = lane & 15;
    const int d = blockIdx.x * 8 + warp;

    float a[8];
#pragma unroll
    for (int j = 0; j < 8; j++) a[j] = 0.0f;

    if (half == 0) {
        uint4 v = *(const uint4*)&ht[(size_t)d * HTW + sub * 8];
        const __half2* h2 = (const __half2*)&v;
#pragma unroll
        for (int j = 0; j < 4; j++) {
            float2 f = __half22float2(h2[j]);
            a[2 * j]     = f.x;
            a[2 * j + 1] = f.y;
        }
    }

    const float4 iv = *(const float4*)&inv[d * 4];
    const int e0 = __ldg(&off[d]);
    const int e1 = __ldg(&off[d + 1]);

    for (int e = e0; e < e1; e += 4) {
#pragma unroll
        for (int q = 0; q < 2; q++) {
            int i = e + half + q * 2;
            if (i < e1) {
                int p = __ldg(&elist[i]);
                int src = p >> 2;
                int r = p & 3;
                float s = (r & 1) ? ((r & 2) ? iv.w : iv.y) : ((r & 2) ? iv.z : iv.x);
                uint4 v = *(const uint4*)&ht[(size_t)src * HTW + (1 + r) * Hc + sub * 8];
                const __half2* h2 = (const __half2*)&v;
#pragma unroll
                for (int j = 0; j < 4; j++) {
                    float2 f = __half22float2(h2[j]);
                    a[2 * j]     += s * f.x;
                    a[2 * j + 1] += s * f.y;
                }
            }
        }
    }

#pragma unroll
    for (int j = 0; j < 8; j++) a[j] += __shfl_xor_sync(0xffffffffu, a[j], 16);

    float sum = 0.f, sq = 0.f;
#pragma unroll
    for (int j = 0; j < 8; j++) { sum += a[j]; sq += a[j] * a[j]; }
#pragma unroll
    for (int o = 8; o; o >>= 1) {
        sum += __shfl_xor_sync(0xffffffffu, sum, o);
        sq  += __shfl_xor_sync(0xffffffffu, sq, o);
    }
    const float inv128 = 1.0f / 128.0f;
    float mu  = sum * inv128;
    float var = sq * inv128 - mu * mu;
    float rs  = rsqrtf(var + 1e-5f);

    float o8[8];
    float4 gv0  = *(const float4*)&lng[sub * 8];
    float4 gv1  = *(const float4*)&lng[sub * 8 + 4];
    float4 lb0  = *(const float4*)&lnb[sub * 8];
    float4 lb1  = *(const float4*)&lnb[sub * 8 + 4];
    const float gg[8] = {gv0.x, gv0.y, gv0.z, gv0.w, gv1.x, gv1.y, gv1.z, gv1.w};
    const float bb[8] = {lb0.x, lb0.y, lb0.z, lb0.w, lb1.x, lb1.y, lb1.z, lb1.w};
#pragma unroll
    for (int j = 0; j < 8; j++)
        o8[j] = fmaxf((a[j] - mu) * rs * gg[j] + bb[j], 0.0f);

    if (HEAD) {
        float4 w0 = *(const float4*)&Wout[sub * 8];
        float4 w1 = *(const float4*)&Wout[sub * 8 + 4];
        const float ww[8] = {w0.x, w0.y, w0.z, w0.w, w1.x, w1.y, w1.z, w1.w};
        float s = 0.f;
#pragma unroll
        for (int j = 0; j < 8; j++) s += o8[j] * ww[j];
#pragma unroll
        for (int o = 8; o; o >>= 1) s += __shfl_xor_sync(0xffffffffu, s, o);
        if (lane == 0) ((float*)out_v)[d] = basep[0] + s + bout[0];
    } else {
        if (half == 0) {
            __half2 p0 = __floats2half2_rn(o8[0], o8[1]);
            __half2 p1 = __floats2half2_rn(o8[2], o8[3]);
            __half2 p2 = __floats2half2_rn(o8[4], o8[5]);
            __half2 p3 = __floats2half2_rn(o8[6], o8[7]);
            uint4 u = make_uint4(*(uint32_t*)&p0, *(uint32_t*)&p1,
                                 *(uint32_t*)&p2, *(uint32_t*)&p3);
            *(uint4*)&((__half*)out_v)[(size_t)d * Hc + sub * 8] = u;
        }
    }
}

// ---------------- launch ----------------
extern "C" void kernel_launch(void* const* d_in, const int* in_sizes, int n_in,
                              void* d_out, int out_size)
{
    const float* xa     = (const float*)d_in[0];
    const float* xw     = (const float*)d_in[1];
    const int*   ei     = (const int*)  d_in[2];
    const int*   et     = (const int*)  d_in[3];
    const float* W_in_a = (const float*)d_in[4];
    const float* b_in_a = (const float*)d_in[5];
    const float* W_in_w = (const float*)d_in[6];
    const float* b_in_w = (const float*)d_in[7];
    const float* W_rel  = (const float*)d_in[8];   // [2,4,128,128]
    const float* W_root = (const float*)d_in[9];   // [2,128,128]
    const float* b_conv = (const float*)d_in[10];  // [2,128]
    const float* ln_g   = (const float*)d_in[11];
    const float* ln_b   = (const float*)d_in[12];
    const float* W_out  = (const float*)d_in[13];
    const float* b_out  = (const float*)d_in[14];
    const float* base   = (const float*)d_in[15];
    float* pred = (float*)d_out;

    void *p_h0, *p_h1, *p_ht, *p_wt, *p_inv, *p_cnt, *p_off, *p_cur, *p_elist, *p_bsum;
    cudaGetSymbolAddress(&p_h0, g_h0);
    cudaGetSymbolAddress(&p_h1, g_h1);
    cudaGetSymbolAddress(&p_ht, g_ht);
    cudaGetSymbolAddress(&p_wt, g_wt);
    cudaGetSymbolAddress(&p_inv, g_inv);
    cudaGetSymbolAddress(&p_cnt, g_cnt);
    cudaGetSymbolAddress(&p_off, g_off);
    cudaGetSymbolAddress(&p_cur, g_cur);
    cudaGetSymbolAddress(&p_elist, g_elist);
    cudaGetSymbolAddress(&p_bsum, g_bsum);
    __half* h0  = (__half*)p_h0;
    __half* h1  = (__half*)p_h1;
    __half* ht  = (__half*)p_ht;
    __half* wt  = (__half*)p_wt;
    float*  inv = (float*)p_inv;
    int* cnt   = (int*)p_cnt;
    int* off   = (int*)p_off;
    int* cur   = (int*)p_cur;
    int* elist = (int*)p_elist;
    int* bsum  = (int*)p_bsum;

    static bool attr_set = false;
    if (!attr_set) {
        cudaFuncSetAttribute(ht_gemm_f16,
                             cudaFuncAttributeMaxDynamicSharedMemorySize,
                             128 * CLDC * sizeof(float));
        cudaFuncSetAttribute(inproj_f16,
                             cudaFuncAttributeMaxDynamicSharedMemorySize,
                             128 * CLDC * sizeof(float));
        attr_set = true;
    }
    const int gemm_smem = 128 * CLDC * sizeof(float);   // 67.6 KB

    // ---- CSR build + weight prep ----
    cudaMemsetAsync(cnt, 0, (size_t)Nc * Rc * sizeof(int));
    count_kernel<<<Ec / 256, 256>>>(ei, et, cnt);
    prep_wt<<<704, 256>>>(W_in_a, W_in_w, W_root, W_rel, wt);
    scan1_kernel<<<256, 256>>>(cnt, inv, off, bsum);
    scan2_kernel<<<1, 256>>>(bsum);
    scan3_kernel<<<Nc / 256, 256>>>(off, bsum, cur);
    fill_kernel<<<Ec / 256, 256>>>(ei, et, cur, elist);

    // ---- input projections -> h0 (fp16) ----
    inproj_f16<<<NAc / 128, 256, gemm_smem>>>(xa, wt, b_in_a, h0);
    inproj_f16<<<NWc / 128, 256, gemm_smem>>>(xw, wt + 8192, b_in_w, h0 + (size_t)NAc * Hc);

    // ---- layer 0 ----
    ht_gemm_f16<<<dim3(5, Nc / 128), 256, gemm_smem>>>(
        h0, wt, 0, b_conv, ht, Nc);
    gather_ln_kernel<false><<<Nc / 8, 256>>>(ht, off, elist, inv,
                                             ln_g, ln_b, h1,
                                             nullptr, nullptr, nullptr);

    // ---- layer 1 (root cols only for assignment nodes; fused output head) ----
    ht_gemm_f16<<<dim3(5, Nc / 128), 256, gemm_smem>>>(
        h1, wt, 1, b_conv + Hc, ht, NAc);
    gather_ln_kernel<true><<<NAc / 8, 256>>>(ht, off, elist, inv,
                                             ln_g + Hc, ln_b + Hc, pred,
                                             W_out, b_out, base);
}